// round 6
// baseline (speedup 1.0000x reference)
#include <cuda_runtime.h>
#include <cuda_bf16.h>

#define NNODES 100000
#define NEDGES 800000
#define ETOT   900000
#define MAXHC  240
#define MAXH   10
#define NEG_SLOPE 0.2f
#define SCAN_BLK 1024
#define NSCAN ((NNODES + SCAN_BLK - 1) / SCAN_BLK)   // 98

// ---------------- scratch (device globals; no allocation allowed) ----------------
__device__ float    g_h   [NNODES * MAXHC];
__device__ float    g_buf0[NNODES * MAXHC];
__device__ float    g_buf1[NNODES * MAXHC];
__device__ float    g_as  [NNODES * MAXH];
__device__ float    g_ad  [NNODES * MAXH];
__device__ float    g_z   [NNODES * MAXH];      // segsum of exp
__device__ float    g_e   [ETOT   * MAXH];      // per-edge exp values
__device__ unsigned g_smaxu[MAXH];              // per-head global max (encoded)
// CSR (built once per launch)
__device__ int g_rowptr [NNODES + 1];
__device__ int g_cnt    [NNODES];
__device__ int g_fill   [NNODES];
__device__ int g_csr_src[ETOT];
__device__ int g_csr_eid[ETOT];
__device__ int g_bsum   [NSCAN];

// ---------------- helpers ----------------
__device__ __forceinline__ unsigned enc_f(float v) {
    unsigned u = __float_as_uint(v);
    return (u & 0x80000000u) ? ~u : (u | 0x80000000u);
}
__device__ __forceinline__ float dec_f(unsigned u) {
    return __uint_as_float((u & 0x80000000u) ? (u ^ 0x80000000u) : ~u);
}

#define PACK2(out, lo, hi) \
    asm("mov.b64 %0, {%1, %2};" : "=l"(out) : "r"(__float_as_uint(lo)), "r"(__float_as_uint(hi)))
#define FMA2(d, a, b) \
    asm("fma.rn.f32x2 %0, %1, %2, %0;" : "+l"(d) : "l"(a), "l"(b))
#define UNPACK2(lo, hi, in) \
    asm("mov.b64 {%0, %1}, %2;" : "=r"(lo), "=r"(hi) : "l"(in))

// ================= CSR build (once per launch) =================
__global__ __launch_bounds__(256) void csr_zero(int* cnt, int* fill, unsigned* smaxu) {
    int i = blockIdx.x * blockDim.x + threadIdx.x;
    if (i < NNODES) { cnt[i] = 0; fill[i] = 0; }
    if (i < MAXH) smaxu[i] = 0u;
}

__global__ __launch_bounds__(256) void csr_hist(const int* __restrict__ ei, int* cnt) {
    int e = blockIdx.x * blockDim.x + threadIdx.x;
    if (e >= ETOT) return;
    int d = (e < NEDGES) ? __ldg(ei + NEDGES + e) : (e - NEDGES);
    atomicAdd(&cnt[d], 1);
}

__global__ __launch_bounds__(SCAN_BLK) void csr_scan1(const int* __restrict__ cnt,
                                                      int* rowptr, int* bsum) {
    __shared__ int sh[SCAN_BLK];
    int gi = blockIdx.x * SCAN_BLK + threadIdx.x;
    int v = (gi < NNODES) ? cnt[gi] : 0;
    sh[threadIdx.x] = v;
    __syncthreads();
    for (int off = 1; off < SCAN_BLK; off <<= 1) {
        int t = (threadIdx.x >= off) ? sh[threadIdx.x - off] : 0;
        __syncthreads();
        sh[threadIdx.x] += t;
        __syncthreads();
    }
    if (gi < NNODES) rowptr[gi] = sh[threadIdx.x] - v;
    if (threadIdx.x == SCAN_BLK - 1) bsum[blockIdx.x] = sh[threadIdx.x];
}

// parallel exclusive scan over NSCAN (<=128) block sums
__global__ __launch_bounds__(128) void csr_scan2(int* bsum) {
    __shared__ int sh[128];
    int v = (threadIdx.x < NSCAN) ? bsum[threadIdx.x] : 0;
    sh[threadIdx.x] = v;
    __syncthreads();
    for (int off = 1; off < 128; off <<= 1) {
        int t = (threadIdx.x >= off) ? sh[threadIdx.x - off] : 0;
        __syncthreads();
        sh[threadIdx.x] += t;
        __syncthreads();
    }
    if (threadIdx.x < NSCAN) bsum[threadIdx.x] = sh[threadIdx.x] - v;
}

__global__ __launch_bounds__(SCAN_BLK) void csr_scan3(int* rowptr, const int* __restrict__ bsum) {
    int gi = blockIdx.x * SCAN_BLK + threadIdx.x;
    if (gi < NNODES) rowptr[gi] += bsum[blockIdx.x];
    if (gi == 0) rowptr[NNODES] = ETOT;
}

__global__ __launch_bounds__(256) void csr_fill(const int* __restrict__ ei,
                                                const int* __restrict__ rowptr,
                                                int* fill, int* csr_src, int* csr_eid) {
    int e = blockIdx.x * blockDim.x + threadIdx.x;
    if (e >= ETOT) return;
    int s, d;
    if (e < NEDGES) { s = __ldg(ei + e); d = __ldg(ei + NEDGES + e); }
    else            { s = e - NEDGES; d = s; }
    int pos = rowptr[d] + atomicAdd(&fill[d], 1);
    csr_src[pos] = s;
    csr_eid[pos] = e;
}

// ================= SGEMM: BM=256, BN=64, BK=8, 256 thr, tile 16x4 =================
// out[M,N] = act(A)[M,K] @ W[K,N]; act = HASB ? relu(a+bias[k]) : a
template<int K, int N, bool HASB>
__global__ __launch_bounds__(256) void gemm_act_kernel(
    const float* __restrict__ A, const float* __restrict__ W,
    const float* __restrict__ bias, float* __restrict__ out, int M)
{
    __shared__ float As[8][256];
    __shared__ float Bs[8][64];

    const int tid  = threadIdx.x;
    const int row0 = blockIdx.y * 256;
    const int col0 = blockIdx.x * 64;

    const int ty = tid >> 4;        // 0..15 -> 16 rows each (8 pairs)
    const int tx = tid & 15;        // 0..15 -> 4 cols each

    const int brow = tid >> 5;             // 0..7
    const int bcol = (tid & 31) * 2;       // 0..62

    unsigned long long acc[8][4];
#pragma unroll
    for (int i = 0; i < 8; i++)
#pragma unroll
        for (int j = 0; j < 4; j++) acc[i][j] = 0ULL;

#pragma unroll 1
    for (int k0 = 0; k0 < K; k0 += 8) {
        // --- A tile: thread t loads row row0+t, cols k0..k0+7 ---
        float4 av0 = make_float4(0.f, 0.f, 0.f, 0.f);
        float4 av1 = make_float4(0.f, 0.f, 0.f, 0.f);
        int gr = row0 + tid;
        if (gr < M) {
            av0 = *(const float4*)(A + (long)gr * K + k0);
            av1 = *(const float4*)(A + (long)gr * K + k0 + 4);
            if (HASB) {
                av0.x = fmaxf(av0.x + __ldg(bias + k0 + 0), 0.f);
                av0.y = fmaxf(av0.y + __ldg(bias + k0 + 1), 0.f);
                av0.z = fmaxf(av0.z + __ldg(bias + k0 + 2), 0.f);
                av0.w = fmaxf(av0.w + __ldg(bias + k0 + 3), 0.f);
                av1.x = fmaxf(av1.x + __ldg(bias + k0 + 4), 0.f);
                av1.y = fmaxf(av1.y + __ldg(bias + k0 + 5), 0.f);
                av1.z = fmaxf(av1.z + __ldg(bias + k0 + 6), 0.f);
                av1.w = fmaxf(av1.w + __ldg(bias + k0 + 7), 0.f);
            }
        }
        As[0][tid] = av0.x; As[1][tid] = av0.y;
        As[2][tid] = av0.z; As[3][tid] = av0.w;
        As[4][tid] = av1.x; As[5][tid] = av1.y;
        As[6][tid] = av1.z; As[7][tid] = av1.w;

        // --- B tile ---
        float2 bv = make_float2(0.f, 0.f);
        int gc = col0 + bcol;
        if (gc + 1 < N)      bv = *(const float2*)(W + (long)(k0 + brow) * N + gc);
        else if (gc < N)     bv.x = W[(long)(k0 + brow) * N + gc];
        Bs[brow][bcol]     = bv.x;
        Bs[brow][bcol + 1] = bv.y;

        __syncthreads();

#pragma unroll
        for (int k = 0; k < 8; k++) {
            const unsigned long long* ap =
                (const unsigned long long*)&As[k][ty * 16];
            unsigned long long a[8];
#pragma unroll
            for (int i = 0; i < 8; i++) a[i] = ap[i];
            const float4 b4 = *(const float4*)&Bs[k][tx * 4];
            unsigned long long bb[4];
            PACK2(bb[0], b4.x, b4.x);
            PACK2(bb[1], b4.y, b4.y);
            PACK2(bb[2], b4.z, b4.z);
            PACK2(bb[3], b4.w, b4.w);
#pragma unroll
            for (int i = 0; i < 8; i++) {
                FMA2(acc[i][0], a[i], bb[0]);
                FMA2(acc[i][1], a[i], bb[1]);
                FMA2(acc[i][2], a[i], bb[2]);
                FMA2(acc[i][3], a[i], bb[3]);
            }
        }
        __syncthreads();
    }

#pragma unroll
    for (int i = 0; i < 8; i++) {
        int r = row0 + ty * 16 + 2 * i;
#pragma unroll
        for (int j = 0; j < 4; j++) {
            int c = col0 + tx * 4 + j;
            unsigned lo, hi;
            UNPACK2(lo, hi, acc[i][j]);
            if (c < N) {
                if (r     < M) out[(long)(r)     * N + c] = __uint_as_float(lo);
                if (r + 1 < M) out[(long)(r + 1) * N + c] = __uint_as_float(hi);
            }
        }
    }
}

// ================= alpha + z=0 + per-head global max =================
template<int H, int C>
__global__ __launch_bounds__(256) void alpha_kernel(
    const float* __restrict__ h, const float* __restrict__ a_s,
    const float* __restrict__ a_d, float* __restrict__ alpha_s,
    float* __restrict__ alpha_d, float* __restrict__ z,
    unsigned* __restrict__ smaxu)
{
    __shared__ unsigned s_max[H];
    if (threadIdx.x < H) s_max[threadIdx.x] = 0u;
    __syncthreads();

    int idx = blockIdx.x * blockDim.x + threadIdx.x;
    if (idx < NNODES * H) {
        int node = idx / H;
        int hh = idx - node * H;
        const float4* hp  = (const float4*)(h + (long)node * H * C + hh * C);
        const float4* asp = (const float4*)(a_s + hh * C);
        const float4* adp = (const float4*)(a_d + hh * C);
        float ss = 0.f, sd = 0.f;
#pragma unroll
        for (int c = 0; c < C / 4; c++) {
            float4 v = hp[c];
            float4 s4 = __ldg(asp + c);
            float4 d4 = __ldg(adp + c);
            ss += v.x * s4.x + v.y * s4.y + v.z * s4.z + v.w * s4.w;
            sd += v.x * d4.x + v.y * d4.y + v.z * d4.z + v.w * d4.w;
        }
        alpha_s[idx] = ss;
        alpha_d[idx] = sd;
        z[idx] = 0.0f;
        atomicMax(&s_max[hh], enc_f(ss));
    }
    __syncthreads();
    if (threadIdx.x < H)
        atomicMax(&smaxu[threadIdx.x], s_max[threadIdx.x]);
}

// ================= fused edge pass: exp(e - m_ub), segsum z =================
template<int H>
__global__ __launch_bounds__(256) void edge_fused(
    const int* __restrict__ ei, const float* __restrict__ as,
    const float* __restrict__ ad, const unsigned* __restrict__ smaxu,
    float* __restrict__ ebuf, float* __restrict__ z)
{
    int idx = blockIdx.x * blockDim.x + threadIdx.x;
    if (idx >= ETOT * H) return;
    int e  = idx / H;
    int hh = idx - e * H;
    int s, d;
    if (e < NEDGES) { s = __ldg(ei + e); d = __ldg(ei + NEDGES + e); }
    else            { s = e - NEDGES; d = s; }
    float asv = __ldg(as + s * H + hh);
    float adv = __ldg(ad + d * H + hh);
    float ev = asv + adv;
    ev = (ev > 0.f) ? ev : NEG_SLOPE * ev;
    float mb = dec_f(__ldg(smaxu + hh)) + adv;
    mb = (mb > 0.f) ? mb : NEG_SLOPE * mb;
    float ex = __expf(ev - mb);
    ebuf[idx] = ex;
    atomicAdd(&z[d * H + hh], ex);
}

// ================= CSR gather: out[n] = (1/z[n]) * sum ex*h[src] =================
// also resets smaxu for the next layer's alpha pass.
template<int H, int C>
__global__ __launch_bounds__(256) void node_gather(
    const int* __restrict__ rowptr, const int* __restrict__ csr_src,
    const int* __restrict__ csr_eid, const float* __restrict__ ex,
    const float* __restrict__ z, const float* __restrict__ h,
    float* __restrict__ out, unsigned* __restrict__ smaxu)
{
    constexpr int NCH = H * C / 4;
    constexpr int HC  = H * C;
    long idx = (long)blockIdx.x * blockDim.x + threadIdx.x;
    if (idx < MAXH) smaxu[idx] = 0u;
    if (idx >= (long)NNODES * NCH) return;
    int n = (int)(idx / NCH);
    int q = (int)(idx - (long)n * NCH);
    int head = q / (C / 4);

    int beg = __ldg(rowptr + n);
    int end = __ldg(rowptr + n + 1);
    float4 acc = make_float4(0.f, 0.f, 0.f, 0.f);
    for (int j = beg; j < end; j++) {
        int s   = __ldg(csr_src + j);
        int eid = __ldg(csr_eid + j);
        float a = __ldg(ex + (long)eid * H + head);
        float4 hv = *(const float4*)(h + (long)s * HC + q * 4);
        acc.x += hv.x * a; acc.y += hv.y * a;
        acc.z += hv.z * a; acc.w += hv.w * a;
    }
    float rzv = __frcp_rn(__ldg(z + (long)n * H + head));
    *(float4*)(out + (long)n * HC + q * 4) =
        make_float4(acc.x * rzv, acc.y * rzv, acc.z * rzv, acc.w * rzv);
}

// ================= epilogue =================
__global__ __launch_bounds__(256) void epilogue_kernel(
    const float* __restrict__ in, const float* __restrict__ bias,
    float* __restrict__ out, int n, int width)
{
    int i = blockIdx.x * blockDim.x + threadIdx.x;
    if (i >= n) return;
    out[i] = fmaxf(in[i] + __ldg(bias + (i % width)), 0.f);
}

// ================= per-layer templated driver =================
template<int DIN, int H, int C, bool HASB>
static void run_layer(const float* cur_in, const float* cur_bias,
                      const float* W, const float* a_s, const float* a_d,
                      const int* ei, float* h, float* as, float* ad,
                      float* z, float* ebuf, unsigned* smaxu,
                      const int* rowptr, const int* csr_src, const int* csr_eid,
                      float* outb)
{
    constexpr int HC = H * C;
    {
        dim3 grid((HC + 63) / 64, (NNODES + 255) / 256);
        gemm_act_kernel<DIN, HC, HASB><<<grid, 256>>>(cur_in, W, cur_bias, h, NNODES);
    }
    {
        int n = NNODES * H;
        alpha_kernel<H, C><<<(n + 255) / 256, 256>>>(h, a_s, a_d, as, ad, z, smaxu);
    }
    {
        int n = ETOT * H;
        edge_fused<H><<<(n + 255) / 256, 256>>>(ei, as, ad, smaxu, ebuf, z);
    }
    {
        long total = (long)NNODES * (HC / 4);
        int blocks = (int)((total + 255) / 256);
        node_gather<H, C><<<blocks, 256>>>(rowptr, csr_src, csr_eid, ebuf, z, h, outb, smaxu);
    }
}

// ================= host orchestration =================
extern "C" void kernel_launch(void* const* d_in, const int* in_sizes, int n_in,
                              void* d_out, int out_size)
{
    const float* x  = (const float*)d_in[0];
    const int*   ei = (const int*)d_in[1];

    float *h, *buf0, *buf1, *as, *ad, *z, *ebuf;
    unsigned* smaxu;
    int *rowptr, *cnt, *fill, *csr_src, *csr_eid, *bsum;
    {
        void* p;
        cudaGetSymbolAddress(&p, g_h);       h       = (float*)p;
        cudaGetSymbolAddress(&p, g_buf0);    buf0    = (float*)p;
        cudaGetSymbolAddress(&p, g_buf1);    buf1    = (float*)p;
        cudaGetSymbolAddress(&p, g_as);      as      = (float*)p;
        cudaGetSymbolAddress(&p, g_ad);      ad      = (float*)p;
        cudaGetSymbolAddress(&p, g_z);       z       = (float*)p;
        cudaGetSymbolAddress(&p, g_e);       ebuf    = (float*)p;
        cudaGetSymbolAddress(&p, g_smaxu);   smaxu   = (unsigned*)p;
        cudaGetSymbolAddress(&p, g_rowptr);  rowptr  = (int*)p;
        cudaGetSymbolAddress(&p, g_cnt);     cnt     = (int*)p;
        cudaGetSymbolAddress(&p, g_fill);    fill    = (int*)p;
        cudaGetSymbolAddress(&p, g_csr_src); csr_src = (int*)p;
        cudaGetSymbolAddress(&p, g_csr_eid); csr_eid = (int*)p;
        cudaGetSymbolAddress(&p, g_bsum);    bsum    = (int*)p;
    }

    // ---- CSR build (graph identical for all 5 layers) ----
    csr_zero<<<(NNODES + 255) / 256, 256>>>(cnt, fill, smaxu);
    csr_hist<<<(ETOT + 255) / 256, 256>>>(ei, cnt);
    csr_scan1<<<NSCAN, SCAN_BLK>>>(cnt, rowptr, bsum);
    csr_scan2<<<1, 128>>>(bsum);
    csr_scan3<<<NSCAN, SCAN_BLK>>>(rowptr, bsum);
    csr_fill<<<(ETOT + 255) / 256, 256>>>(ei, rowptr, fill, csr_src, csr_eid);

    const float* W[5]; const float* B[5]; const float* AS[5]; const float* AD[5];
    for (int i = 0; i < 5; i++) {
        W[i]  = (const float*)d_in[3 + 4 * i];
        B[i]  = (const float*)d_in[4 + 4 * i];
        AS[i] = (const float*)d_in[5 + 4 * i];
        AD[i] = (const float*)d_in[6 + 4 * i];
    }

    run_layer< 32, 10, 24, false>(x,    nullptr, W[0], AS[0], AD[0], ei, h, as, ad, z, ebuf, smaxu, rowptr, csr_src, csr_eid, buf0);
    run_layer<240,  5, 24, true >(buf0, B[0],    W[1], AS[1], AD[1], ei, h, as, ad, z, ebuf, smaxu, rowptr, csr_src, csr_eid, buf1);
    run_layer<120,  2, 24, true >(buf1, B[1],    W[2], AS[2], AD[2], ei, h, as, ad, z, ebuf, smaxu, rowptr, csr_src, csr_eid, buf0);
    run_layer< 48,  1, 24, true >(buf0, B[2],    W[3], AS[3], AD[3], ei, h, as, ad, z, ebuf, smaxu, rowptr, csr_src, csr_eid, buf1);
    run_layer< 24,  1, 12, true >(buf1, B[3],    W[4], AS[4], AD[4], ei, h, as, ad, z, ebuf, smaxu, rowptr, csr_src, csr_eid, buf0);

    {
        int n = NNODES * 12;
        epilogue_kernel<<<(n + 255) / 256, 256>>>(buf0, B[4], (float*)d_out, n, 12);
    }
}

// round 7
// speedup vs baseline: 1.1230x; 1.1230x over previous
#include <cuda_runtime.h>
#include <cuda_bf16.h>

#define NNODES 100000
#define NEDGES 800000
#define ETOT   900000
#define MAXHC  240
#define MAXH   10
#define NEG_SLOPE 0.2f
#define SCAN_BLK 1024
#define NSCAN ((NNODES + SCAN_BLK - 1) / SCAN_BLK)   // 98

// ---------------- scratch (device globals; no allocation allowed) ----------------
__device__ float    g_h   [NNODES * MAXHC];
__device__ float    g_buf0[NNODES * MAXHC];
__device__ float    g_buf1[NNODES * MAXHC];
__device__ float    g_as  [NNODES * MAXH];
__device__ float    g_ad  [NNODES * MAXH];
__device__ float    g_z   [NNODES * MAXH];      // segsum of exp
__device__ float    g_e   [ETOT   * MAXH];      // per-edge exp values (CSR order)
__device__ unsigned g_smaxu[MAXH];              // per-head global max (encoded)
// CSR (built once per launch)
__device__ int g_rowptr [NNODES + 1];
__device__ int g_cnt    [NNODES];
__device__ int g_fill   [NNODES];
__device__ int g_csr_src[ETOT];
__device__ int g_epos   [ETOT];                 // edge id -> csr position
__device__ int g_bsum   [NSCAN];

// ---------------- helpers ----------------
__device__ __forceinline__ unsigned enc_f(float v) {
    unsigned u = __float_as_uint(v);
    return (u & 0x80000000u) ? ~u : (u | 0x80000000u);
}
__device__ __forceinline__ float dec_f(unsigned u) {
    return __uint_as_float((u & 0x80000000u) ? (u ^ 0x80000000u) : ~u);
}

#define PACK2(out, lo, hi) \
    asm("mov.b64 %0, {%1, %2};" : "=l"(out) : "r"(__float_as_uint(lo)), "r"(__float_as_uint(hi)))
#define FMA2(d, a, b) \
    asm("fma.rn.f32x2 %0, %1, %2, %0;" : "+l"(d) : "l"(a), "l"(b))
#define UNPACK2(lo, hi, in) \
    asm("mov.b64 {%0, %1}, %2;" : "=r"(lo), "=r"(hi) : "l"(in))

// ================= CSR build (once per launch) =================
__global__ __launch_bounds__(256) void csr_zero(int* cnt, int* fill, unsigned* smaxu) {
    int i = blockIdx.x * blockDim.x + threadIdx.x;
    if (i < NNODES) { cnt[i] = 0; fill[i] = 0; }
    if (i < MAXH) smaxu[i] = 0u;
}

__global__ __launch_bounds__(256) void csr_hist(const int* __restrict__ ei, int* cnt) {
    int e = blockIdx.x * blockDim.x + threadIdx.x;
    if (e >= ETOT) return;
    int d = (e < NEDGES) ? __ldg(ei + NEDGES + e) : (e - NEDGES);
    atomicAdd(&cnt[d], 1);
}

__global__ __launch_bounds__(SCAN_BLK) void csr_scan1(const int* __restrict__ cnt,
                                                      int* rowptr, int* bsum) {
    __shared__ int sh[SCAN_BLK];
    int gi = blockIdx.x * SCAN_BLK + threadIdx.x;
    int v = (gi < NNODES) ? cnt[gi] : 0;
    sh[threadIdx.x] = v;
    __syncthreads();
    for (int off = 1; off < SCAN_BLK; off <<= 1) {
        int t = (threadIdx.x >= off) ? sh[threadIdx.x - off] : 0;
        __syncthreads();
        sh[threadIdx.x] += t;
        __syncthreads();
    }
    if (gi < NNODES) rowptr[gi] = sh[threadIdx.x] - v;
    if (threadIdx.x == SCAN_BLK - 1) bsum[blockIdx.x] = sh[threadIdx.x];
}

__global__ __launch_bounds__(128) void csr_scan2(int* bsum) {
    __shared__ int sh[128];
    int v = (threadIdx.x < NSCAN) ? bsum[threadIdx.x] : 0;
    sh[threadIdx.x] = v;
    __syncthreads();
    for (int off = 1; off < 128; off <<= 1) {
        int t = (threadIdx.x >= off) ? sh[threadIdx.x - off] : 0;
        __syncthreads();
        sh[threadIdx.x] += t;
        __syncthreads();
    }
    if (threadIdx.x < NSCAN) bsum[threadIdx.x] = sh[threadIdx.x] - v;
}

__global__ __launch_bounds__(SCAN_BLK) void csr_scan3(int* rowptr, const int* __restrict__ bsum) {
    int gi = blockIdx.x * SCAN_BLK + threadIdx.x;
    if (gi < NNODES) rowptr[gi] += bsum[blockIdx.x];
    if (gi == 0) rowptr[NNODES] = ETOT;
}

__global__ __launch_bounds__(256) void csr_fill(const int* __restrict__ ei,
                                                const int* __restrict__ rowptr,
                                                int* fill, int* csr_src, int* epos) {
    int e = blockIdx.x * blockDim.x + threadIdx.x;
    if (e >= ETOT) return;
    int s, d;
    if (e < NEDGES) { s = __ldg(ei + e); d = __ldg(ei + NEDGES + e); }
    else            { s = e - NEDGES; d = s; }
    int pos = rowptr[d] + atomicAdd(&fill[d], 1);
    csr_src[pos] = s;
    epos[e] = pos;
}

// ================= SGEMM (round-5 layout): BM=128, BN=64, BK=8, 8x4 tile =================
template<int K, int N, bool HASB>
__global__ __launch_bounds__(256) void gemm_act_kernel(
    const float* __restrict__ A, const float* __restrict__ W,
    const float* __restrict__ bias, float* __restrict__ out, int M)
{
    __shared__ float As[8][128];
    __shared__ float Bs[8][64];

    const int tid  = threadIdx.x;
    const int row0 = blockIdx.y * 128;
    const int col0 = blockIdx.x * 64;

    const int ty = tid >> 4;
    const int tx = tid & 15;

    const int arow = tid >> 1;
    const int acol = (tid & 1) * 4;
    const int brow = tid >> 5;
    const int bcol = (tid & 31) * 2;

    unsigned long long acc[4][4];
#pragma unroll
    for (int i = 0; i < 4; i++)
#pragma unroll
        for (int j = 0; j < 4; j++) acc[i][j] = 0ULL;

#pragma unroll 1
    for (int k0 = 0; k0 < K; k0 += 8) {
        float4 av = make_float4(0.f, 0.f, 0.f, 0.f);
        int gr = row0 + arow;
        if (gr < M) {
            av = *(const float4*)(A + (long)gr * K + k0 + acol);
            if (HASB) {
                av.x = fmaxf(av.x + __ldg(bias + k0 + acol + 0), 0.f);
                av.y = fmaxf(av.y + __ldg(bias + k0 + acol + 1), 0.f);
                av.z = fmaxf(av.z + __ldg(bias + k0 + acol + 2), 0.f);
                av.w = fmaxf(av.w + __ldg(bias + k0 + acol + 3), 0.f);
            }
        }
        As[acol + 0][arow] = av.x;
        As[acol + 1][arow] = av.y;
        As[acol + 2][arow] = av.z;
        As[acol + 3][arow] = av.w;

        float2 bv = make_float2(0.f, 0.f);
        int gc = col0 + bcol;
        if (gc + 1 < N)      bv = *(const float2*)(W + (long)(k0 + brow) * N + gc);
        else if (gc < N)     bv.x = W[(long)(k0 + brow) * N + gc];
        Bs[brow][bcol]     = bv.x;
        Bs[brow][bcol + 1] = bv.y;

        __syncthreads();

#pragma unroll
        for (int k = 0; k < 8; k++) {
            const unsigned long long* ap =
                (const unsigned long long*)&As[k][ty * 8];
            unsigned long long a01 = ap[0], a23 = ap[1], a45 = ap[2], a67 = ap[3];
            const float4 b4 = *(const float4*)&Bs[k][tx * 4];
            unsigned long long bb[4];
            PACK2(bb[0], b4.x, b4.x);
            PACK2(bb[1], b4.y, b4.y);
            PACK2(bb[2], b4.z, b4.z);
            PACK2(bb[3], b4.w, b4.w);
#pragma unroll
            for (int j = 0; j < 4; j++) {
                FMA2(acc[0][j], a01, bb[j]);
                FMA2(acc[1][j], a23, bb[j]);
                FMA2(acc[2][j], a45, bb[j]);
                FMA2(acc[3][j], a67, bb[j]);
            }
        }
        __syncthreads();
    }

#pragma unroll
    for (int i = 0; i < 4; i++) {
        int r = row0 + ty * 8 + 2 * i;
#pragma unroll
        for (int j = 0; j < 4; j++) {
            int c = col0 + tx * 4 + j;
            unsigned lo, hi;
            UNPACK2(lo, hi, acc[i][j]);
            if (c < N) {
                if (r     < M) out[(long)(r)     * N + c] = __uint_as_float(lo);
                if (r + 1 < M) out[(long)(r + 1) * N + c] = __uint_as_float(hi);
            }
        }
    }
}

// ================= alpha + z=0 + per-head global max =================
template<int H, int C>
__global__ __launch_bounds__(256) void alpha_kernel(
    const float* __restrict__ h, const float* __restrict__ a_s,
    const float* __restrict__ a_d, float* __restrict__ alpha_s,
    float* __restrict__ alpha_d, float* __restrict__ z,
    unsigned* __restrict__ smaxu)
{
    __shared__ unsigned s_max[H];
    if (threadIdx.x < H) s_max[threadIdx.x] = 0u;
    __syncthreads();

    int idx = blockIdx.x * blockDim.x + threadIdx.x;
    if (idx < NNODES * H) {
        int node = idx / H;
        int hh = idx - node * H;
        const float4* hp  = (const float4*)(h + (long)node * H * C + hh * C);
        const float4* asp = (const float4*)(a_s + hh * C);
        const float4* adp = (const float4*)(a_d + hh * C);
        float ss = 0.f, sd = 0.f;
#pragma unroll
        for (int c = 0; c < C / 4; c++) {
            float4 v = hp[c];
            float4 s4 = __ldg(asp + c);
            float4 d4 = __ldg(adp + c);
            ss += v.x * s4.x + v.y * s4.y + v.z * s4.z + v.w * s4.w;
            sd += v.x * d4.x + v.y * d4.y + v.z * d4.z + v.w * d4.w;
        }
        alpha_s[idx] = ss;
        alpha_d[idx] = sd;
        z[idx] = 0.0f;
        atomicMax(&s_max[hh], enc_f(ss));
    }
    __syncthreads();
    if (threadIdx.x < H)
        atomicMax(&smaxu[threadIdx.x], s_max[threadIdx.x]);
}

// ================= fused edge pass: exp(e - m_ub), segsum z, CSR-ordered store =================
template<int H>
__global__ __launch_bounds__(256) void edge_fused(
    const int* __restrict__ ei, const int* __restrict__ epos,
    const float* __restrict__ as, const float* __restrict__ ad,
    const unsigned* __restrict__ smaxu,
    float* __restrict__ ebuf, float* __restrict__ z)
{
    int idx = blockIdx.x * blockDim.x + threadIdx.x;
    if (idx >= ETOT * H) return;
    int e  = idx / H;
    int hh = idx - e * H;
    int s, d;
    if (e < NEDGES) { s = __ldg(ei + e); d = __ldg(ei + NEDGES + e); }
    else            { s = e - NEDGES; d = s; }
    float asv = __ldg(as + s * H + hh);
    float adv = __ldg(ad + d * H + hh);
    float ev = asv + adv;
    ev = (ev > 0.f) ? ev : NEG_SLOPE * ev;
    float mb = dec_f(__ldg(smaxu + hh)) + adv;
    mb = (mb > 0.f) ? mb : NEG_SLOPE * mb;
    float ex = __expf(ev - mb);
    int pos = __ldg(epos + e);
    ebuf[(long)pos * H + hh] = ex;      // scattered write (fire-and-forget)
    atomicAdd(&z[d * H + hh], ex);
}

// ================= CSR gather: out[n] = (1/z[n]) * sum ex*h[src] =================
// ex now in CSR order -> contiguous reads along j. Also resets smaxu for next layer.
template<int H, int C>
__global__ __launch_bounds__(256) void node_gather(
    const int* __restrict__ rowptr, const int* __restrict__ csr_src,
    const float* __restrict__ ex, const float* __restrict__ z,
    const float* __restrict__ h, float* __restrict__ out,
    unsigned* __restrict__ smaxu)
{
    constexpr int NCH = H * C / 4;
    constexpr int HC  = H * C;
    long idx = (long)blockIdx.x * blockDim.x + threadIdx.x;
    if (idx < MAXH) smaxu[idx] = 0u;
    if (idx >= (long)NNODES * NCH) return;
    int n = (int)(idx / NCH);
    int q = (int)(idx - (long)n * NCH);
    int head = q / (C / 4);

    int beg = __ldg(rowptr + n);
    int end = __ldg(rowptr + n + 1);
    float4 acc = make_float4(0.f, 0.f, 0.f, 0.f);
    for (int j = beg; j < end; j++) {
        int s   = __ldg(csr_src + j);
        float a = __ldg(ex + (long)j * H + head);
        float4 hv = *(const float4*)(h + (long)s * HC + q * 4);
        acc.x += hv.x * a; acc.y += hv.y * a;
        acc.z += hv.z * a; acc.w += hv.w * a;
    }
    float rzv = __frcp_rn(__ldg(z + (long)n * H + head));
    *(float4*)(out + (long)n * HC + q * 4) =
        make_float4(acc.x * rzv, acc.y * rzv, acc.z * rzv, acc.w * rzv);
}

// ================= epilogue =================
__global__ __launch_bounds__(256) void epilogue_kernel(
    const float* __restrict__ in, const float* __restrict__ bias,
    float* __restrict__ out, int n, int width)
{
    int i = blockIdx.x * blockDim.x + threadIdx.x;
    if (i >= n) return;
    out[i] = fmaxf(in[i] + __ldg(bias + (i % width)), 0.f);
}

// ================= per-layer templated driver (minus GEMM) =================
template<int H, int C>
static void run_layer_rest(const float* a_s, const float* a_d,
                           const int* ei, const int* epos,
                           float* h, float* as, float* ad,
                           float* z, float* ebuf, unsigned* smaxu,
                           const int* rowptr, const int* csr_src,
                           float* outb)
{
    constexpr int HC = H * C;
    {
        int n = NNODES * H;
        alpha_kernel<H, C><<<(n + 255) / 256, 256>>>(h, a_s, a_d, as, ad, z, smaxu);
    }
    {
        int n = ETOT * H;
        edge_fused<H><<<(n + 255) / 256, 256>>>(ei, epos, as, ad, smaxu, ebuf, z);
    }
    {
        long total = (long)NNODES * (HC / 4);
        int blocks = (int)((total + 255) / 256);
        node_gather<H, C><<<blocks, 256>>>(rowptr, csr_src, ebuf, z, h, outb, smaxu);
    }
}

template<int K, int N, bool HASB>
static void launch_gemm(const float* A, const float* W, const float* bias, float* out) {
    dim3 grid((N + 63) / 64, (NNODES + 127) / 128);
    gemm_act_kernel<K, N, HASB><<<grid, 256>>>(A, W, bias, out, NNODES);
}

// ================= host orchestration =================
extern "C" void kernel_launch(void* const* d_in, const int* in_sizes, int n_in,
                              void* d_out, int out_size)
{
    const float* x  = (const float*)d_in[0];
    const int*   ei = (const int*)d_in[1];

    float *h, *buf0, *buf1, *as, *ad, *z, *ebuf;
    unsigned* smaxu;
    int *rowptr, *cnt, *fill, *csr_src, *epos, *bsum;
    {
        void* p;
        cudaGetSymbolAddress(&p, g_h);       h       = (float*)p;
        cudaGetSymbolAddress(&p, g_buf0);    buf0    = (float*)p;
        cudaGetSymbolAddress(&p, g_buf1);    buf1    = (float*)p;
        cudaGetSymbolAddress(&p, g_as);      as      = (float*)p;
        cudaGetSymbolAddress(&p, g_ad);      ad      = (float*)p;
        cudaGetSymbolAddress(&p, g_z);       z       = (float*)p;
        cudaGetSymbolAddress(&p, g_e);       ebuf    = (float*)p;
        cudaGetSymbolAddress(&p, g_smaxu);   smaxu   = (unsigned*)p;
        cudaGetSymbolAddress(&p, g_rowptr);  rowptr  = (int*)p;
        cudaGetSymbolAddress(&p, g_cnt);     cnt     = (int*)p;
        cudaGetSymbolAddress(&p, g_fill);    fill    = (int*)p;
        cudaGetSymbolAddress(&p, g_csr_src); csr_src = (int*)p;
        cudaGetSymbolAddress(&p, g_epos);    epos    = (int*)p;
        cudaGetSymbolAddress(&p, g_bsum);    bsum    = (int*)p;
    }

    const float* W[5]; const float* B[5]; const float* AS[5]; const float* AD[5];
    for (int i = 0; i < 5; i++) {
        W[i]  = (const float*)d_in[3 + 4 * i];
        B[i]  = (const float*)d_in[4 + 4 * i];
        AS[i] = (const float*)d_in[5 + 4 * i];
        AD[i] = (const float*)d_in[6 + 4 * i];
    }

    // ---- CSR build interleaved with layer-0 GEMM (independent);
    //      GEMM is launch #4 so the profiler captures it ----
    csr_zero<<<(NNODES + 255) / 256, 256>>>(cnt, fill, smaxu);          // #1
    csr_hist<<<(ETOT + 255) / 256, 256>>>(ei, cnt);                     // #2
    csr_scan1<<<NSCAN, SCAN_BLK>>>(cnt, rowptr, bsum);                  // #3
    launch_gemm< 32, 240, false>(x, W[0], nullptr, h);                  // #4 (profiled)
    csr_scan2<<<1, 128>>>(bsum);                                        // #5
    csr_scan3<<<NSCAN, SCAN_BLK>>>(rowptr, bsum);                       // #6
    csr_fill<<<(ETOT + 255) / 256, 256>>>(ei, rowptr, fill, csr_src, epos); // #7

    // ---- layer 0 rest ----
    run_layer_rest<10, 24>(AS[0], AD[0], ei, epos, h, as, ad, z, ebuf, smaxu, rowptr, csr_src, buf0);

    // ---- layers 1-4 ----
    launch_gemm<240, 120, true >(buf0, W[1], B[0], h);
    run_layer_rest< 5, 24>(AS[1], AD[1], ei, epos, h, as, ad, z, ebuf, smaxu, rowptr, csr_src, buf1);

    launch_gemm<120,  48, true >(buf1, W[2], B[1], h);
    run_layer_rest< 2, 24>(AS[2], AD[2], ei, epos, h, as, ad, z, ebuf, smaxu, rowptr, csr_src, buf0);

    launch_gemm< 48,  24, true >(buf0, W[3], B[2], h);
    run_layer_rest< 1, 24>(AS[3], AD[3], ei, epos, h, as, ad, z, ebuf, smaxu, rowptr, csr_src, buf1);

    launch_gemm< 24,  12, true >(buf1, W[4], B[3], h);
    run_layer_rest< 1, 12>(AS[4], AD[4], ei, epos, h, as, ad, z, ebuf, smaxu, rowptr, csr_src, buf0);

    {
        int n = NNODES * 12;
        epilogue_kernel<<<(n + 255) / 256, 256>>>(buf0, B[4], (float*)d_out, n, 12);
    }
}

// round 8
// speedup vs baseline: 1.1494x; 1.0235x over previous
#include <cuda_runtime.h>
#include <cuda_bf16.h>

#define NNODES 100000
#define NEDGES 800000
#define ETOT   900000
#define MAXHC  240
#define MAXH   10
#define NEG_SLOPE 0.2f
#define SCAN_BLK 1024
#define NSCAN ((NNODES + SCAN_BLK - 1) / SCAN_BLK)   // 98

// ---------------- scratch (device globals; no allocation allowed) ----------------
__device__ float    g_h   [NNODES * MAXHC];
__device__ float    g_buf0[NNODES * MAXHC];
__device__ float    g_buf1[NNODES * MAXHC];
__device__ float    g_as  [NNODES * MAXH];
__device__ float    g_ad  [NNODES * MAXH];
__device__ float    g_e   [ETOT   * MAXH];      // per-edge exp values (CSR order)
__device__ unsigned g_smaxu[MAXH];              // per-head global max (encoded)
// CSR (built once per launch)
__device__ int g_rowptr [NNODES + 1];
__device__ int g_cnt    [NNODES];
__device__ int g_fill   [NNODES];
__device__ int g_csr_src[ETOT];
__device__ int g_epos   [ETOT];                 // edge id -> csr position
__device__ int g_bsum   [NSCAN];

// ---------------- helpers ----------------
__device__ __forceinline__ unsigned enc_f(float v) {
    unsigned u = __float_as_uint(v);
    return (u & 0x80000000u) ? ~u : (u | 0x80000000u);
}
__device__ __forceinline__ float dec_f(unsigned u) {
    return __uint_as_float((u & 0x80000000u) ? (u ^ 0x80000000u) : ~u);
}

#define PACK2(out, lo, hi) \
    asm("mov.b64 %0, {%1, %2};" : "=l"(out) : "r"(__float_as_uint(lo)), "r"(__float_as_uint(hi)))
#define FMA2(d, a, b) \
    asm("fma.rn.f32x2 %0, %1, %2, %0;" : "+l"(d) : "l"(a), "l"(b))
#define UNPACK2(lo, hi, in) \
    asm("mov.b64 {%0, %1}, %2;" : "=r"(lo), "=r"(hi) : "l"(in))

// ================= CSR build (once per launch) =================
__global__ __launch_bounds__(256) void csr_zero(int* cnt, int* fill, unsigned* smaxu) {
    int i = blockIdx.x * blockDim.x + threadIdx.x;
    if (i < NNODES) { cnt[i] = 0; fill[i] = 0; }
    if (i < MAXH) smaxu[i] = 0u;
}

__global__ __launch_bounds__(256) void csr_hist(const int* __restrict__ ei, int* cnt) {
    int e = blockIdx.x * blockDim.x + threadIdx.x;
    if (e >= ETOT) return;
    int d = (e < NEDGES) ? __ldg(ei + NEDGES + e) : (e - NEDGES);
    atomicAdd(&cnt[d], 1);
}

__global__ __launch_bounds__(SCAN_BLK) void csr_scan1(const int* __restrict__ cnt,
                                                      int* rowptr, int* bsum) {
    __shared__ int sh[SCAN_BLK];
    int gi = blockIdx.x * SCAN_BLK + threadIdx.x;
    int v = (gi < NNODES) ? cnt[gi] : 0;
    sh[threadIdx.x] = v;
    __syncthreads();
    for (int off = 1; off < SCAN_BLK; off <<= 1) {
        int t = (threadIdx.x >= off) ? sh[threadIdx.x - off] : 0;
        __syncthreads();
        sh[threadIdx.x] += t;
        __syncthreads();
    }
    if (gi < NNODES) rowptr[gi] = sh[threadIdx.x] - v;
    if (threadIdx.x == SCAN_BLK - 1) bsum[blockIdx.x] = sh[threadIdx.x];
}

__global__ __launch_bounds__(128) void csr_scan2(int* bsum) {
    __shared__ int sh[128];
    int v = (threadIdx.x < NSCAN) ? bsum[threadIdx.x] : 0;
    sh[threadIdx.x] = v;
    __syncthreads();
    for (int off = 1; off < 128; off <<= 1) {
        int t = (threadIdx.x >= off) ? sh[threadIdx.x - off] : 0;
        __syncthreads();
        sh[threadIdx.x] += t;
        __syncthreads();
    }
    if (threadIdx.x < NSCAN) bsum[threadIdx.x] = sh[threadIdx.x] - v;
}

__global__ __launch_bounds__(SCAN_BLK) void csr_scan3(int* rowptr, const int* __restrict__ bsum) {
    int gi = blockIdx.x * SCAN_BLK + threadIdx.x;
    if (gi < NNODES) rowptr[gi] += bsum[blockIdx.x];
    if (gi == 0) rowptr[NNODES] = ETOT;
}

__global__ __launch_bounds__(256) void csr_fill(const int* __restrict__ ei,
                                                const int* __restrict__ rowptr,
                                                int* fill, int* csr_src, int* epos) {
    int e = blockIdx.x * blockDim.x + threadIdx.x;
    if (e >= ETOT) return;
    int s, d;
    if (e < NEDGES) { s = __ldg(ei + e); d = __ldg(ei + NEDGES + e); }
    else            { s = e - NEDGES; d = s; }
    int pos = rowptr[d] + atomicAdd(&fill[d], 1);
    csr_src[pos] = s;
    epos[e] = pos;
}

// ================= SGEMM: BM=128, BN=64, BK=8, 8x4 tile, double-buffered =================
template<int K, int N, bool HASB>
__global__ __launch_bounds__(256) void gemm_act_kernel(
    const float* __restrict__ A, const float* __restrict__ W,
    const float* __restrict__ bias, float* __restrict__ out, int M)
{
    __shared__ float As[2][8][128];
    __shared__ float Bs[2][8][64];

    const int tid  = threadIdx.x;
    const int row0 = blockIdx.y * 128;
    const int col0 = blockIdx.x * 64;

    const int ty = tid >> 4;
    const int tx = tid & 15;

    const int arow = tid >> 1;
    const int acol = (tid & 1) * 4;
    const int brow = tid >> 5;
    const int bcol = (tid & 31) * 2;

    unsigned long long acc[4][4];
#pragma unroll
    for (int i = 0; i < 4; i++)
#pragma unroll
        for (int j = 0; j < 4; j++) acc[i][j] = 0ULL;

    const int gr = row0 + arow;
    const int gc = col0 + bcol;

    float4 av; float2 bv;

    auto load_g = [&](int k0) {
        av = make_float4(0.f, 0.f, 0.f, 0.f);
        if (gr < M) {
            av = *(const float4*)(A + (long)gr * K + k0 + acol);
            if (HASB) {
                av.x = fmaxf(av.x + __ldg(bias + k0 + acol + 0), 0.f);
                av.y = fmaxf(av.y + __ldg(bias + k0 + acol + 1), 0.f);
                av.z = fmaxf(av.z + __ldg(bias + k0 + acol + 2), 0.f);
                av.w = fmaxf(av.w + __ldg(bias + k0 + acol + 3), 0.f);
            }
        }
        bv = make_float2(0.f, 0.f);
        if (gc + 1 < N)      bv = *(const float2*)(W + (long)(k0 + brow) * N + gc);
        else if (gc < N)     bv.x = W[(long)(k0 + brow) * N + gc];
    };
    auto store_s = [&](int buf) {
        As[buf][acol + 0][arow] = av.x;
        As[buf][acol + 1][arow] = av.y;
        As[buf][acol + 2][arow] = av.z;
        As[buf][acol + 3][arow] = av.w;
        Bs[buf][brow][bcol]     = bv.x;
        Bs[buf][brow][bcol + 1] = bv.y;
    };

    load_g(0);
    store_s(0);
    __syncthreads();

    int cur = 0;
#pragma unroll 1
    for (int k0 = 0; k0 < K; k0 += 8) {
        const bool more = (k0 + 8 < K);
        if (more) load_g(k0 + 8);

#pragma unroll
        for (int k = 0; k < 8; k++) {
            const unsigned long long* ap =
                (const unsigned long long*)&As[cur][k][ty * 8];
            unsigned long long a01 = ap[0], a23 = ap[1], a45 = ap[2], a67 = ap[3];
            const float4 b4 = *(const float4*)&Bs[cur][k][tx * 4];
            unsigned long long bb[4];
            PACK2(bb[0], b4.x, b4.x);
            PACK2(bb[1], b4.y, b4.y);
            PACK2(bb[2], b4.z, b4.z);
            PACK2(bb[3], b4.w, b4.w);
#pragma unroll
            for (int j = 0; j < 4; j++) {
                FMA2(acc[0][j], a01, bb[j]);
                FMA2(acc[1][j], a23, bb[j]);
                FMA2(acc[2][j], a45, bb[j]);
                FMA2(acc[3][j], a67, bb[j]);
            }
        }
        if (more) {
            store_s(cur ^ 1);
            __syncthreads();
        }
        cur ^= 1;
    }

#pragma unroll
    for (int i = 0; i < 4; i++) {
        int r = row0 + ty * 8 + 2 * i;
#pragma unroll
        for (int j = 0; j < 4; j++) {
            int c = col0 + tx * 4 + j;
            unsigned lo, hi;
            UNPACK2(lo, hi, acc[i][j]);
            if (c < N) {
                if (r     < M) out[(long)(r)     * N + c] = __uint_as_float(lo);
                if (r + 1 < M) out[(long)(r + 1) * N + c] = __uint_as_float(hi);
            }
        }
    }
}

// ================= alpha + per-head global max =================
template<int H, int C>
__global__ __launch_bounds__(256) void alpha_kernel(
    const float* __restrict__ h, const float* __restrict__ a_s,
    const float* __restrict__ a_d, float* __restrict__ alpha_s,
    float* __restrict__ alpha_d, unsigned* __restrict__ smaxu)
{
    __shared__ unsigned s_max[H];
    if (threadIdx.x < H) s_max[threadIdx.x] = 0u;
    __syncthreads();

    int idx = blockIdx.x * blockDim.x + threadIdx.x;
    if (idx < NNODES * H) {
        int node = idx / H;
        int hh = idx - node * H;
        const float4* hp  = (const float4*)(h + (long)node * H * C + hh * C);
        const float4* asp = (const float4*)(a_s + hh * C);
        const float4* adp = (const float4*)(a_d + hh * C);
        float ss = 0.f, sd = 0.f;
#pragma unroll
        for (int c = 0; c < C / 4; c++) {
            float4 v = hp[c];
            float4 s4 = __ldg(asp + c);
            float4 d4 = __ldg(adp + c);
            ss += v.x * s4.x + v.y * s4.y + v.z * s4.z + v.w * s4.w;
            sd += v.x * d4.x + v.y * d4.y + v.z * d4.z + v.w * d4.w;
        }
        alpha_s[idx] = ss;
        alpha_d[idx] = sd;
        atomicMax(&s_max[hh], enc_f(ss));
    }
    __syncthreads();
    if (threadIdx.x < H)
        atomicMax(&smaxu[threadIdx.x], s_max[threadIdx.x]);
}

// ================= fused edge pass: exp(e - m_ub), CSR-ordered store =================
// (no z atomics — segment sum is recomputed inline in node_gather)
template<int H>
__global__ __launch_bounds__(256) void edge_fused(
    const int* __restrict__ ei, const int* __restrict__ epos,
    const float* __restrict__ as, const float* __restrict__ ad,
    const unsigned* __restrict__ smaxu, float* __restrict__ ebuf)
{
    int idx = blockIdx.x * blockDim.x + threadIdx.x;
    if (idx >= ETOT * H) return;
    int e  = idx / H;
    int hh = idx - e * H;
    int s, d;
    if (e < NEDGES) { s = __ldg(ei + e); d = __ldg(ei + NEDGES + e); }
    else            { s = e - NEDGES; d = s; }
    float asv = __ldg(as + s * H + hh);
    float adv = __ldg(ad + d * H + hh);
    float ev = asv + adv;
    ev = (ev > 0.f) ? ev : NEG_SLOPE * ev;
    float mb = dec_f(__ldg(smaxu + hh)) + adv;
    mb = (mb > 0.f) ? mb : NEG_SLOPE * mb;
    float ex = __expf(ev - mb);
    int pos = __ldg(epos + e);
    ebuf[(long)pos * H + hh] = ex;      // scattered write (fire-and-forget)
}

// ================= CSR gather: out[n] = (1/sum ex) * sum ex*h[src] =================
// z computed inline (ex already in registers). Also resets smaxu for next layer.
template<int H, int C>
__global__ __launch_bounds__(256) void node_gather(
    const int* __restrict__ rowptr, const int* __restrict__ csr_src,
    const float* __restrict__ ex, const float* __restrict__ h,
    float* __restrict__ out, unsigned* __restrict__ smaxu)
{
    constexpr int NCH = H * C / 4;
    constexpr int HC  = H * C;
    long idx = (long)blockIdx.x * blockDim.x + threadIdx.x;
    if (idx < MAXH) smaxu[idx] = 0u;
    if (idx >= (long)NNODES * NCH) return;
    int n = (int)(idx / NCH);
    int q = (int)(idx - (long)n * NCH);
    int head = q / (C / 4);

    int beg = __ldg(rowptr + n);
    int end = __ldg(rowptr + n + 1);
    float4 acc = make_float4(0.f, 0.f, 0.f, 0.f);
    float zs = 0.f;
    for (int j = beg; j < end; j++) {
        int s   = __ldg(csr_src + j);
        float a = __ldg(ex + (long)j * H + head);
        float4 hv = *(const float4*)(h + (long)s * HC + q * 4);
        acc.x += hv.x * a; acc.y += hv.y * a;
        acc.z += hv.z * a; acc.w += hv.w * a;
        zs += a;
    }
    float rzv = __frcp_rn(zs);
    *(float4*)(out + (long)n * HC + q * 4) =
        make_float4(acc.x * rzv, acc.y * rzv, acc.z * rzv, acc.w * rzv);
}

// ================= epilogue =================
__global__ __launch_bounds__(256) void epilogue_kernel(
    const float* __restrict__ in, const float* __restrict__ bias,
    float* __restrict__ out, int n, int width)
{
    int i = blockIdx.x * blockDim.x + threadIdx.x;
    if (i >= n) return;
    out[i] = fmaxf(in[i] + __ldg(bias + (i % width)), 0.f);
}

// ================= per-layer templated driver (minus GEMM) =================
template<int H, int C>
static void run_layer_rest(const float* a_s, const float* a_d,
                           const int* ei, const int* epos,
                           float* h, float* as, float* ad,
                           float* ebuf, unsigned* smaxu,
                           const int* rowptr, const int* csr_src,
                           float* outb)
{
    constexpr int HC = H * C;
    {
        int n = NNODES * H;
        alpha_kernel<H, C><<<(n + 255) / 256, 256>>>(h, a_s, a_d, as, ad, smaxu);
    }
    {
        int n = ETOT * H;
        edge_fused<H><<<(n + 255) / 256, 256>>>(ei, epos, as, ad, smaxu, ebuf);
    }
    {
        long total = (long)NNODES * (HC / 4);
        int blocks = (int)((total + 255) / 256);
        node_gather<H, C><<<blocks, 256>>>(rowptr, csr_src, ebuf, h, outb, smaxu);
    }
}

template<int K, int N, bool HASB>
static void launch_gemm(const float* A, const float* W, const float* bias, float* out) {
    dim3 grid((N + 63) / 64, (NNODES + 127) / 128);
    gemm_act_kernel<K, N, HASB><<<grid, 256>>>(A, W, bias, out, NNODES);
}

// ================= host orchestration =================
extern "C" void kernel_launch(void* const* d_in, const int* in_sizes, int n_in,
                              void* d_out, int out_size)
{
    const float* x  = (const float*)d_in[0];
    const int*   ei = (const int*)d_in[1];

    float *h, *buf0, *buf1, *as, *ad, *ebuf;
    unsigned* smaxu;
    int *rowptr, *cnt, *fill, *csr_src, *epos, *bsum;
    {
        void* p;
        cudaGetSymbolAddress(&p, g_h);       h       = (float*)p;
        cudaGetSymbolAddress(&p, g_buf0);    buf0    = (float*)p;
        cudaGetSymbolAddress(&p, g_buf1);    buf1    = (float*)p;
        cudaGetSymbolAddress(&p, g_as);      as      = (float*)p;
        cudaGetSymbolAddress(&p, g_ad);      ad      = (float*)p;
        cudaGetSymbolAddress(&p, g_e);       ebuf    = (float*)p;
        cudaGetSymbolAddress(&p, g_smaxu);   smaxu   = (unsigned*)p;
        cudaGetSymbolAddress(&p, g_rowptr);  rowptr  = (int*)p;
        cudaGetSymbolAddress(&p, g_cnt);     cnt     = (int*)p;
        cudaGetSymbolAddress(&p, g_fill);    fill    = (int*)p;
        cudaGetSymbolAddress(&p, g_csr_src); csr_src = (int*)p;
        cudaGetSymbolAddress(&p, g_epos);    epos    = (int*)p;
        cudaGetSymbolAddress(&p, g_bsum);    bsum    = (int*)p;
    }

    const float* W[5]; const float* B[5]; const float* AS[5]; const float* AD[5];
    for (int i = 0; i < 5; i++) {
        W[i]  = (const float*)d_in[3 + 4 * i];
        B[i]  = (const float*)d_in[4 + 4 * i];
        AS[i] = (const float*)d_in[5 + 4 * i];
        AD[i] = (const float*)d_in[6 + 4 * i];
    }

    // ---- CSR build interleaved with layer-0 GEMM (independent);
    //      GEMM is launch #4 so the profiler captures it ----
    csr_zero<<<(NNODES + 255) / 256, 256>>>(cnt, fill, smaxu);          // #1
    csr_hist<<<(ETOT + 255) / 256, 256>>>(ei, cnt);                     // #2
    csr_scan1<<<NSCAN, SCAN_BLK>>>(cnt, rowptr, bsum);                  // #3
    launch_gemm< 32, 240, false>(x, W[0], nullptr, h);                  // #4 (profiled)
    csr_scan2<<<1, 128>>>(bsum);                                        // #5
    csr_scan3<<<NSCAN, SCAN_BLK>>>(rowptr, bsum);                       // #6
    csr_fill<<<(ETOT + 255) / 256, 256>>>(ei, rowptr, fill, csr_src, epos); // #7

    // ---- layer 0 rest ----
    run_layer_rest<10, 24>(AS[0], AD[0], ei, epos, h, as, ad, ebuf, smaxu, rowptr, csr_src, buf0);

    // ---- layers 1-4 ----
    launch_gemm<240, 120, true >(buf0, W[1], B[0], h);
    run_layer_rest< 5, 24>(AS[1], AD[1], ei, epos, h, as, ad, ebuf, smaxu, rowptr, csr_src, buf1);

    launch_gemm<120,  48, true >(buf1, W[2], B[1], h);
    run_layer_rest< 2, 24>(AS[2], AD[2], ei, epos, h, as, ad, ebuf, smaxu, rowptr, csr_src, buf0);

    launch_gemm< 48,  24, true >(buf0, W[3], B[2], h);
    run_layer_rest< 1, 24>(AS[3], AD[3], ei, epos, h, as, ad, ebuf, smaxu, rowptr, csr_src, buf1);

    launch_gemm< 24,  12, true >(buf1, W[4], B[3], h);
    run_layer_rest< 1, 12>(AS[4], AD[4], ei, epos, h, as, ad, ebuf, smaxu, rowptr, csr_src, buf0);

    {
        int n = NNODES * 12;
        epilogue_kernel<<<(n + 255) / 256, 256>>>(buf0, B[4], (float*)d_out, n, 12);
    }
}

// round 9
// speedup vs baseline: 1.1650x; 1.0136x over previous
#include <cuda_runtime.h>
#include <cuda_bf16.h>

#define NNODES 100000
#define NEDGES 800000
#define ETOT   900000
#define MAXHC  240
#define MAXH   10
#define NEG_SLOPE 0.2f
#define SCAN_BLK 1024
#define NSCAN ((NNODES + SCAN_BLK - 1) / SCAN_BLK)   // 98

// ---------------- scratch (device globals; no allocation allowed) ----------------
__device__ float    g_h   [NNODES * MAXHC];
__device__ float    g_buf0[NNODES * MAXHC];
__device__ float    g_buf1[NNODES * MAXHC];
__device__ float    g_as  [NNODES * MAXH];
__device__ float    g_ad  [NNODES * MAXH];
__device__ float    g_e   [ETOT   * MAXH];      // per-edge exp values (CSR order)
__device__ unsigned g_smaxu[MAXH];              // per-head global max (encoded)
// CSR (built once per launch)
__device__ int g_rowptr [NNODES + 1];
__device__ int g_cnt    [NNODES];
__device__ int g_fill   [NNODES];
__device__ int g_csr_src[ETOT];
__device__ int g_epos   [ETOT];                 // edge id -> csr position
__device__ int g_bsum   [NSCAN];

// ---------------- helpers ----------------
__device__ __forceinline__ unsigned enc_f(float v) {
    unsigned u = __float_as_uint(v);
    return (u & 0x80000000u) ? ~u : (u | 0x80000000u);
}
__device__ __forceinline__ float dec_f(unsigned u) {
    return __uint_as_float((u & 0x80000000u) ? (u ^ 0x80000000u) : ~u);
}

#define PACK2(out, lo, hi) \
    asm("mov.b64 %0, {%1, %2};" : "=l"(out) : "r"(__float_as_uint(lo)), "r"(__float_as_uint(hi)))
#define FMA2(d, a, b) \
    asm("fma.rn.f32x2 %0, %1, %2, %0;" : "+l"(d) : "l"(a), "l"(b))
#define UNPACK2(lo, hi, in) \
    asm("mov.b64 {%0, %1}, %2;" : "=r"(lo), "=r"(hi) : "l"(in))

// ================= CSR build (once per launch) =================
__global__ __launch_bounds__(256) void csr_zero(int* cnt, int* fill, unsigned* smaxu) {
    int i = blockIdx.x * blockDim.x + threadIdx.x;
    if (i < NNODES) { cnt[i] = 0; fill[i] = 0; }
    if (i < MAXH) smaxu[i] = 0u;
}

__global__ __launch_bounds__(256) void csr_hist(const int* __restrict__ ei, int* cnt) {
    int e = blockIdx.x * blockDim.x + threadIdx.x;
    if (e >= ETOT) return;
    int d = (e < NEDGES) ? __ldg(ei + NEDGES + e) : (e - NEDGES);
    atomicAdd(&cnt[d], 1);
}

__global__ __launch_bounds__(SCAN_BLK) void csr_scan1(const int* __restrict__ cnt,
                                                      int* rowptr, int* bsum) {
    __shared__ int sh[SCAN_BLK];
    int gi = blockIdx.x * SCAN_BLK + threadIdx.x;
    int v = (gi < NNODES) ? cnt[gi] : 0;
    sh[threadIdx.x] = v;
    __syncthreads();
    for (int off = 1; off < SCAN_BLK; off <<= 1) {
        int t = (threadIdx.x >= off) ? sh[threadIdx.x - off] : 0;
        __syncthreads();
        sh[threadIdx.x] += t;
        __syncthreads();
    }
    if (gi < NNODES) rowptr[gi] = sh[threadIdx.x] - v;
    if (threadIdx.x == SCAN_BLK - 1) bsum[blockIdx.x] = sh[threadIdx.x];
}

__global__ __launch_bounds__(128) void csr_scan2(int* bsum) {
    __shared__ int sh[128];
    int v = (threadIdx.x < NSCAN) ? bsum[threadIdx.x] : 0;
    sh[threadIdx.x] = v;
    __syncthreads();
    for (int off = 1; off < 128; off <<= 1) {
        int t = (threadIdx.x >= off) ? sh[threadIdx.x - off] : 0;
        __syncthreads();
        sh[threadIdx.x] += t;
        __syncthreads();
    }
    if (threadIdx.x < NSCAN) bsum[threadIdx.x] = sh[threadIdx.x] - v;
}

__global__ __launch_bounds__(SCAN_BLK) void csr_scan3(int* rowptr, const int* __restrict__ bsum) {
    int gi = blockIdx.x * SCAN_BLK + threadIdx.x;
    if (gi < NNODES) rowptr[gi] += bsum[blockIdx.x];
    if (gi == 0) rowptr[NNODES] = ETOT;
}

__global__ __launch_bounds__(256) void csr_fill(const int* __restrict__ ei,
                                                const int* __restrict__ rowptr,
                                                int* fill, int* csr_src, int* epos) {
    int e = blockIdx.x * blockDim.x + threadIdx.x;
    if (e >= ETOT) return;
    int s, d;
    if (e < NEDGES) { s = __ldg(ei + e); d = __ldg(ei + NEDGES + e); }
    else            { s = e - NEDGES; d = s; }
    int pos = rowptr[d] + atomicAdd(&fill[d], 1);
    csr_src[pos] = s;
    epos[e] = pos;
}

// ================= SGEMM: BM=128, BN=64, BK=8, 8x4 tile, single buffer, pure =================
template<int K, int N>
__global__ __launch_bounds__(256) void gemm_kernel(
    const float* __restrict__ A, const float* __restrict__ W,
    float* __restrict__ out, int M)
{
    __shared__ float As[8][128];
    __shared__ float Bs[8][64];

    const int tid  = threadIdx.x;
    const int row0 = blockIdx.y * 128;
    const int col0 = blockIdx.x * 64;

    const int ty = tid >> 4;
    const int tx = tid & 15;

    const int arow = tid >> 1;
    const int acol = (tid & 1) * 4;
    const int brow = tid >> 5;
    const int bcol = (tid & 31) * 2;

    unsigned long long acc[4][4];
#pragma unroll
    for (int i = 0; i < 4; i++)
#pragma unroll
        for (int j = 0; j < 4; j++) acc[i][j] = 0ULL;

#pragma unroll 1
    for (int k0 = 0; k0 < K; k0 += 8) {
        float4 av = make_float4(0.f, 0.f, 0.f, 0.f);
        int gr = row0 + arow;
        if (gr < M)
            av = *(const float4*)(A + (long)gr * K + k0 + acol);
        As[acol + 0][arow] = av.x;
        As[acol + 1][arow] = av.y;
        As[acol + 2][arow] = av.z;
        As[acol + 3][arow] = av.w;

        float2 bv = make_float2(0.f, 0.f);
        int gc = col0 + bcol;
        if (gc + 1 < N)      bv = *(const float2*)(W + (long)(k0 + brow) * N + gc);
        else if (gc < N)     bv.x = W[(long)(k0 + brow) * N + gc];
        Bs[brow][bcol]     = bv.x;
        Bs[brow][bcol + 1] = bv.y;

        __syncthreads();

#pragma unroll
        for (int k = 0; k < 8; k++) {
            const unsigned long long* ap =
                (const unsigned long long*)&As[k][ty * 8];
            unsigned long long a01 = ap[0], a23 = ap[1], a45 = ap[2], a67 = ap[3];
            const float4 b4 = *(const float4*)&Bs[k][tx * 4];
            unsigned long long bb[4];
            PACK2(bb[0], b4.x, b4.x);
            PACK2(bb[1], b4.y, b4.y);
            PACK2(bb[2], b4.z, b4.z);
            PACK2(bb[3], b4.w, b4.w);
#pragma unroll
            for (int j = 0; j < 4; j++) {
                FMA2(acc[0][j], a01, bb[j]);
                FMA2(acc[1][j], a23, bb[j]);
                FMA2(acc[2][j], a45, bb[j]);
                FMA2(acc[3][j], a67, bb[j]);
            }
        }
        __syncthreads();
    }

#pragma unroll
    for (int i = 0; i < 4; i++) {
        int r = row0 + ty * 8 + 2 * i;
#pragma unroll
        for (int j = 0; j < 4; j++) {
            int c = col0 + tx * 4 + j;
            unsigned lo, hi;
            UNPACK2(lo, hi, acc[i][j]);
            if (c < N) {
                if (r     < M) out[(long)(r)     * N + c] = __uint_as_float(lo);
                if (r + 1 < M) out[(long)(r + 1) * N + c] = __uint_as_float(hi);
            }
        }
    }
}

// ================= alpha + per-head global max =================
template<int H, int C>
__global__ __launch_bounds__(256) void alpha_kernel(
    const float* __restrict__ h, const float* __restrict__ a_s,
    const float* __restrict__ a_d, float* __restrict__ alpha_s,
    float* __restrict__ alpha_d, unsigned* __restrict__ smaxu)
{
    __shared__ unsigned s_max[H];
    if (threadIdx.x < H) s_max[threadIdx.x] = 0u;
    __syncthreads();

    int idx = blockIdx.x * blockDim.x + threadIdx.x;
    if (idx < NNODES * H) {
        int node = idx / H;
        int hh = idx - node * H;
        const float4* hp  = (const float4*)(h + (long)node * H * C + hh * C);
        const float4* asp = (const float4*)(a_s + hh * C);
        const float4* adp = (const float4*)(a_d + hh * C);
        float ss = 0.f, sd = 0.f;
#pragma unroll
        for (int c = 0; c < C / 4; c++) {
            float4 v = hp[c];
            float4 s4 = __ldg(asp + c);
            float4 d4 = __ldg(adp + c);
            ss += v.x * s4.x + v.y * s4.y + v.z * s4.z + v.w * s4.w;
            sd += v.x * d4.x + v.y * d4.y + v.z * d4.z + v.w * d4.w;
        }
        alpha_s[idx] = ss;
        alpha_d[idx] = sd;
        atomicMax(&s_max[hh], enc_f(ss));
    }
    __syncthreads();
    if (threadIdx.x < H)
        atomicMax(&smaxu[threadIdx.x], s_max[threadIdx.x]);
}

// ================= fused edge pass: exp(e - m_ub), CSR-ordered store =================
template<int H>
__global__ __launch_bounds__(256) void edge_fused(
    const int* __restrict__ ei, const int* __restrict__ epos,
    const float* __restrict__ as, const float* __restrict__ ad,
    const unsigned* __restrict__ smaxu, float* __restrict__ ebuf)
{
    int idx = blockIdx.x * blockDim.x + threadIdx.x;
    if (idx >= ETOT * H) return;
    int e  = idx / H;
    int hh = idx - e * H;
    int s, d;
    if (e < NEDGES) { s = __ldg(ei + e); d = __ldg(ei + NEDGES + e); }
    else            { s = e - NEDGES; d = s; }
    float asv = __ldg(as + s * H + hh);
    float adv = __ldg(ad + d * H + hh);
    float ev = asv + adv;
    ev = (ev > 0.f) ? ev : NEG_SLOPE * ev;
    float mb = dec_f(__ldg(smaxu + hh)) + adv;
    mb = (mb > 0.f) ? mb : NEG_SLOPE * mb;
    float ex = __expf(ev - mb);
    int pos = __ldg(epos + e);
    ebuf[(long)pos * H + hh] = ex;      // scattered write (fire-and-forget)
}

// ================= CSR gather + bias + ReLU epilogue =================
// out[n] = relu( (sum_j ex*h[src]) / (sum_j ex) + bias[col] )
// 2-way unrolled edge loop for MLP. Also resets smaxu for the next layer.
template<int H, int C>
__global__ __launch_bounds__(256) void node_gather(
    const int* __restrict__ rowptr, const int* __restrict__ csr_src,
    const float* __restrict__ ex, const float* __restrict__ h,
    const float* __restrict__ bias, float* __restrict__ out,
    unsigned* __restrict__ smaxu)
{
    constexpr int NCH = H * C / 4;
    constexpr int HC  = H * C;
    long idx = (long)blockIdx.x * blockDim.x + threadIdx.x;
    if (idx < MAXH) smaxu[idx] = 0u;
    if (idx >= (long)NNODES * NCH) return;
    int n = (int)(idx / NCH);
    int q = (int)(idx - (long)n * NCH);
    int head = q / (C / 4);

    int beg = __ldg(rowptr + n);
    int end = __ldg(rowptr + n + 1);
    float4 acc = make_float4(0.f, 0.f, 0.f, 0.f);
    float zs = 0.f;
    int j = beg;
    for (; j + 1 < end; j += 2) {
        int s0 = __ldg(csr_src + j);
        int s1 = __ldg(csr_src + j + 1);
        float a0 = __ldg(ex + (long)j * H + head);
        float a1 = __ldg(ex + (long)(j + 1) * H + head);
        float4 h0 = *(const float4*)(h + (long)s0 * HC + q * 4);
        float4 h1 = *(const float4*)(h + (long)s1 * HC + q * 4);
        acc.x += h0.x * a0; acc.y += h0.y * a0;
        acc.z += h0.z * a0; acc.w += h0.w * a0;
        acc.x += h1.x * a1; acc.y += h1.y * a1;
        acc.z += h1.z * a1; acc.w += h1.w * a1;
        zs += a0 + a1;
    }
    if (j < end) {
        int s0 = __ldg(csr_src + j);
        float a0 = __ldg(ex + (long)j * H + head);
        float4 h0 = *(const float4*)(h + (long)s0 * HC + q * 4);
        acc.x += h0.x * a0; acc.y += h0.y * a0;
        acc.z += h0.z * a0; acc.w += h0.w * a0;
        zs += a0;
    }
    float rzv = __frcp_rn(zs);
    const float4 bv = __ldg((const float4*)(bias + q * 4));
    *(float4*)(out + (long)n * HC + q * 4) =
        make_float4(fmaxf(acc.x * rzv + bv.x, 0.f),
                    fmaxf(acc.y * rzv + bv.y, 0.f),
                    fmaxf(acc.z * rzv + bv.z, 0.f),
                    fmaxf(acc.w * rzv + bv.w, 0.f));
}

// ================= per-layer templated driver (minus GEMM) =================
template<int H, int C>
static void run_layer_rest(const float* a_s, const float* a_d, const float* bias,
                           const int* ei, const int* epos,
                           float* h, float* as, float* ad,
                           float* ebuf, unsigned* smaxu,
                           const int* rowptr, const int* csr_src,
                           float* outb)
{
    constexpr int HC = H * C;
    {
        int n = NNODES * H;
        alpha_kernel<H, C><<<(n + 255) / 256, 256>>>(h, a_s, a_d, as, ad, smaxu);
    }
    {
        int n = ETOT * H;
        edge_fused<H><<<(n + 255) / 256, 256>>>(ei, epos, as, ad, smaxu, ebuf);
    }
    {
        long total = (long)NNODES * (HC / 4);
        int blocks = (int)((total + 255) / 256);
        node_gather<H, C><<<blocks, 256>>>(rowptr, csr_src, ebuf, h, bias, outb, smaxu);
    }
}

template<int K, int N>
static void launch_gemm(const float* A, const float* W, float* out) {
    dim3 grid((N + 63) / 64, (NNODES + 127) / 128);
    gemm_kernel<K, N><<<grid, 256>>>(A, W, out, NNODES);
}

// ================= host orchestration =================
extern "C" void kernel_launch(void* const* d_in, const int* in_sizes, int n_in,
                              void* d_out, int out_size)
{
    const float* x  = (const float*)d_in[0];
    const int*   ei = (const int*)d_in[1];

    float *h, *buf0, *buf1, *as, *ad, *ebuf;
    unsigned* smaxu;
    int *rowptr, *cnt, *fill, *csr_src, *epos, *bsum;
    {
        void* p;
        cudaGetSymbolAddress(&p, g_h);       h       = (float*)p;
        cudaGetSymbolAddress(&p, g_buf0);    buf0    = (float*)p;
        cudaGetSymbolAddress(&p, g_buf1);    buf1    = (float*)p;
        cudaGetSymbolAddress(&p, g_as);      as      = (float*)p;
        cudaGetSymbolAddress(&p, g_ad);      ad      = (float*)p;
        cudaGetSymbolAddress(&p, g_e);       ebuf    = (float*)p;
        cudaGetSymbolAddress(&p, g_smaxu);   smaxu   = (unsigned*)p;
        cudaGetSymbolAddress(&p, g_rowptr);  rowptr  = (int*)p;
        cudaGetSymbolAddress(&p, g_cnt);     cnt     = (int*)p;
        cudaGetSymbolAddress(&p, g_fill);    fill    = (int*)p;
        cudaGetSymbolAddress(&p, g_csr_src); csr_src = (int*)p;
        cudaGetSymbolAddress(&p, g_epos);    epos    = (int*)p;
        cudaGetSymbolAddress(&p, g_bsum);    bsum    = (int*)p;
    }

    const float* W[5]; const float* B[5]; const float* AS[5]; const float* AD[5];
    for (int i = 0; i < 5; i++) {
        W[i]  = (const float*)d_in[3 + 4 * i];
        B[i]  = (const float*)d_in[4 + 4 * i];
        AS[i] = (const float*)d_in[5 + 4 * i];
        AD[i] = (const float*)d_in[6 + 4 * i];
    }

    // ---- CSR build interleaved with layer-0 GEMM (independent) ----
    csr_zero<<<(NNODES + 255) / 256, 256>>>(cnt, fill, smaxu);          // #1
    csr_hist<<<(ETOT + 255) / 256, 256>>>(ei, cnt);                     // #2
    csr_scan1<<<NSCAN, SCAN_BLK>>>(cnt, rowptr, bsum);                  // #3
    launch_gemm< 32, 240>(x, W[0], h);                                  // #4 (profiled)
    csr_scan2<<<1, 128>>>(bsum);                                        // #5
    csr_scan3<<<NSCAN, SCAN_BLK>>>(rowptr, bsum);                       // #6
    csr_fill<<<(ETOT + 255) / 256, 256>>>(ei, rowptr, fill, csr_src, epos); // #7

    // ---- layer 0 rest (gather applies bias B[0] + relu -> x1) ----
    run_layer_rest<10, 24>(AS[0], AD[0], B[0], ei, epos, h, as, ad, ebuf, smaxu, rowptr, csr_src, buf0);

    // ---- layers 1-4 (gather of layer i applies B[i] + relu) ----
    launch_gemm<240, 120>(buf0, W[1], h);
    run_layer_rest< 5, 24>(AS[1], AD[1], B[1], ei, epos, h, as, ad, ebuf, smaxu, rowptr, csr_src, buf1);

    launch_gemm<120,  48>(buf1, W[2], h);
    run_layer_rest< 2, 24>(AS[2], AD[2], B[2], ei, epos, h, as, ad, ebuf, smaxu, rowptr, csr_src, buf0);

    launch_gemm< 48,  24>(buf0, W[3], h);
    run_layer_rest< 1, 24>(AS[3], AD[3], B[3], ei, epos, h, as, ad, ebuf, smaxu, rowptr, csr_src, buf1);

    launch_gemm< 24,  12>(buf1, W[4], h);
    run_layer_rest< 1, 12>(AS[4], AD[4], B[4], ei, epos, h, as, ad, ebuf, smaxu, rowptr, csr_src, (float*)d_out);
}

// round 10
// speedup vs baseline: 1.3007x; 1.1165x over previous
#include <cuda_runtime.h>
#include <cuda_bf16.h>

#define NNODES 100000
#define NEDGES 800000
#define ETOT   900000
#define MAXHC  240
#define MAXH   10
#define NEG_SLOPE 0.2f
#define SCAN_BLK 1024
#define NSCAN ((NNODES + SCAN_BLK - 1) / SCAN_BLK)   // 98

// ---------------- scratch (device globals; no allocation allowed) ----------------
__device__ float    g_h   [NNODES * MAXHC];
__device__ float    g_buf0[NNODES * MAXHC];
__device__ float    g_buf1[NNODES * MAXHC];
__device__ float    g_as  [NNODES * MAXH];
__device__ float    g_ad  [NNODES * MAXH];
__device__ float    g_e   [ETOT   * MAXH];      // per-edge exp values (CSR order)
__device__ unsigned g_smaxu[MAXH];              // per-head global max (encoded)
// CSR (built once per launch)
__device__ int g_rowptr [NNODES + 1];
__device__ int g_cnt    [NNODES];
__device__ int g_fill   [NNODES];
__device__ int g_csr_src[ETOT];
__device__ int g_epos   [ETOT];                 // edge id -> csr position
__device__ int g_bsum   [NSCAN];

// ---------------- helpers ----------------
__device__ __forceinline__ unsigned enc_f(float v) {
    unsigned u = __float_as_uint(v);
    return (u & 0x80000000u) ? ~u : (u | 0x80000000u);
}
__device__ __forceinline__ float dec_f(unsigned u) {
    return __uint_as_float((u & 0x80000000u) ? (u ^ 0x80000000u) : ~u);
}

// split fp32 into two tf32 values (3xTF32 trick); x - hi is exact in fp32.
__device__ __forceinline__ void split_tf32(float x, unsigned& hi, unsigned& lo) {
    asm("cvt.rna.tf32.f32 %0, %1;" : "=r"(hi) : "f"(x));
    float r = x - __uint_as_float(hi);
    asm("cvt.rna.tf32.f32 %0, %1;" : "=r"(lo) : "f"(r));
}

__device__ __forceinline__ void mma_tf32(float* d, const unsigned* a, const unsigned* b) {
    asm volatile("mma.sync.aligned.m16n8k8.row.col.f32.tf32.tf32.f32 "
        "{%0,%1,%2,%3}, {%4,%5,%6,%7}, {%8,%9}, {%0,%1,%2,%3};"
        : "+f"(d[0]), "+f"(d[1]), "+f"(d[2]), "+f"(d[3])
        : "r"(a[0]), "r"(a[1]), "r"(a[2]), "r"(a[3]), "r"(b[0]), "r"(b[1]));
}

#define CP_ASYNC16(dst, src, sz) \
    asm volatile("cp.async.ca.shared.global [%0], [%1], 16, %2;" \
                 :: "r"(dst), "l"(src), "r"(sz) : "memory")
#define CP_COMMIT()  asm volatile("cp.async.commit_group;" ::: "memory")
#define CP_WAIT1()   asm volatile("cp.async.wait_group 1;" ::: "memory")
#define CP_WAIT0()   asm volatile("cp.async.wait_group 0;" ::: "memory")

// ================= CSR build (once per launch) =================
__global__ __launch_bounds__(256) void csr_zero(int* cnt, int* fill, unsigned* smaxu) {
    int i = blockIdx.x * blockDim.x + threadIdx.x;
    if (i < NNODES) { cnt[i] = 0; fill[i] = 0; }
    if (i < MAXH) smaxu[i] = 0u;
}

__global__ __launch_bounds__(256) void csr_hist(const int* __restrict__ ei, int* cnt) {
    int e = blockIdx.x * blockDim.x + threadIdx.x;
    if (e >= ETOT) return;
    int d = (e < NEDGES) ? __ldg(ei + NEDGES + e) : (e - NEDGES);
    atomicAdd(&cnt[d], 1);
}

__global__ __launch_bounds__(SCAN_BLK) void csr_scan1(const int* __restrict__ cnt,
                                                      int* rowptr, int* bsum) {
    __shared__ int sh[SCAN_BLK];
    int gi = blockIdx.x * SCAN_BLK + threadIdx.x;
    int v = (gi < NNODES) ? cnt[gi] : 0;
    sh[threadIdx.x] = v;
    __syncthreads();
    for (int off = 1; off < SCAN_BLK; off <<= 1) {
        int t = (threadIdx.x >= off) ? sh[threadIdx.x - off] : 0;
        __syncthreads();
        sh[threadIdx.x] += t;
        __syncthreads();
    }
    if (gi < NNODES) rowptr[gi] = sh[threadIdx.x] - v;
    if (threadIdx.x == SCAN_BLK - 1) bsum[blockIdx.x] = sh[threadIdx.x];
}

__global__ __launch_bounds__(128) void csr_scan2(int* bsum) {
    __shared__ int sh[128];
    int v = (threadIdx.x < NSCAN) ? bsum[threadIdx.x] : 0;
    sh[threadIdx.x] = v;
    __syncthreads();
    for (int off = 1; off < 128; off <<= 1) {
        int t = (threadIdx.x >= off) ? sh[threadIdx.x - off] : 0;
        __syncthreads();
        sh[threadIdx.x] += t;
        __syncthreads();
    }
    if (threadIdx.x < NSCAN) bsum[threadIdx.x] = sh[threadIdx.x] - v;
}

__global__ __launch_bounds__(SCAN_BLK) void csr_scan3(int* rowptr, const int* __restrict__ bsum) {
    int gi = blockIdx.x * SCAN_BLK + threadIdx.x;
    if (gi < NNODES) rowptr[gi] += bsum[blockIdx.x];
    if (gi == 0) rowptr[NNODES] = ETOT;
}

__global__ __launch_bounds__(256) void csr_fill(const int* __restrict__ ei,
                                                const int* __restrict__ rowptr,
                                                int* fill, int* csr_src, int* epos) {
    int e = blockIdx.x * blockDim.x + threadIdx.x;
    if (e >= ETOT) return;
    int s, d;
    if (e < NEDGES) { s = __ldg(ei + e); d = __ldg(ei + NEDGES + e); }
    else            { s = e - NEDGES; d = s; }
    int pos = rowptr[d] + atomicAdd(&fill[d], 1);
    csr_src[pos] = s;
    epos[e] = pos;
}

// ================= tf32 tensor-core GEMM: out[M,N] = A[M,K] @ W[K,N] =================
// Block 128x64, 8 warps (4m x 2n), warp tile 32x32 (2x4 m16n8 frags).
// cp.async double-buffered tiles; 3xTF32 split per fragment for fp32 accuracy.
template<int K, int N>
__global__ __launch_bounds__(256, 3) void gemm_tf32_kernel(
    const float* __restrict__ A, const float* __restrict__ W,
    float* __restrict__ out, int M)
{
    __shared__ float As[2][128][12];   // [row][k0..7], pad 12 => conflict-free frags
    __shared__ float Bs[2][8][72];     // [k][n0..63],  pad 72 => conflict-free frags

    const int tid  = threadIdx.x;
    const int lane = tid & 31;
    const int warp = tid >> 5;
    const int wm   = warp & 3;          // 0..3 -> 32-row stripe
    const int wn   = warp >> 2;         // 0..1 -> 32-col stripe
    const int row0 = blockIdx.y * 128;
    const int col0 = blockIdx.x * 64;

    float acc[2][4][4];
#pragma unroll
    for (int mt = 0; mt < 2; mt++)
#pragma unroll
        for (int nt = 0; nt < 4; nt++)
#pragma unroll
            for (int i = 0; i < 4; i++) acc[mt][nt][i] = 0.f;

    // ---- cp.async source/dest (A: thread -> 16B of one row; B: tid<128) ----
    const int arow = tid >> 1;
    const int ah4  = (tid & 1) * 4;
    const int gr   = row0 + arow;
    const unsigned a_sz = (gr < M) ? 16u : 0u;
    const float* a_src = A + (long)(gr < M ? gr : 0) * K + ah4;
    unsigned a_dst[2];
    a_dst[0] = (unsigned)__cvta_generic_to_shared(&As[0][arow][ah4]);
    a_dst[1] = (unsigned)__cvta_generic_to_shared(&As[1][arow][ah4]);

    const int bk   = (tid & 127) >> 4;      // 0..7
    const int bnc  = tid & 15;              // 0..15 -> 4 floats each
    const int gcol = col0 + bnc * 4;
    int rem = N - gcol;
    const unsigned b_sz = (unsigned)(rem >= 4 ? 16 : (rem > 0 ? rem * 4 : 0));
    const float* b_src = W + (long)bk * N + (rem > 0 ? gcol : 0);
    unsigned b_dst[2];
    b_dst[0] = (unsigned)__cvta_generic_to_shared(&Bs[0][bk][bnc * 4]);
    b_dst[1] = (unsigned)__cvta_generic_to_shared(&Bs[1][bk][bnc * 4]);

    constexpr int NK = K / 8;

    // prologue: stage 0
    CP_ASYNC16(a_dst[0], a_src, a_sz);
    if (tid < 128) CP_ASYNC16(b_dst[0], b_src, b_sz);
    CP_COMMIT();

#pragma unroll 1
    for (int s = 0; s < NK; s++) {
        if (s + 1 < NK) {
            int k0n = (s + 1) * 8;
            CP_ASYNC16(a_dst[(s + 1) & 1], a_src + k0n, a_sz);
            if (tid < 128) CP_ASYNC16(b_dst[(s + 1) & 1], b_src + (long)k0n * N, b_sz);
            CP_COMMIT();
            CP_WAIT1();
        } else {
            CP_WAIT0();
        }
        __syncthreads();

        const int buf = s & 1;
        // A fragments (hi/lo) for 2 m-tiles
        unsigned ahf[2][4], alf[2][4];
#pragma unroll
        for (int mt = 0; mt < 2; mt++) {
            const float* ap = &As[buf][wm * 32 + mt * 16 + (lane >> 2)][lane & 3];
            split_tf32(ap[0],   ahf[mt][0], alf[mt][0]);    // (row, c)
            split_tf32(ap[96],  ahf[mt][1], alf[mt][1]);    // (row+8, c)   8*12
            split_tf32(ap[4],   ahf[mt][2], alf[mt][2]);    // (row, c+4)
            split_tf32(ap[100], ahf[mt][3], alf[mt][3]);    // (row+8, c+4)
        }
        // B fragments per n-tile, 3xTF32 mma
#pragma unroll
        for (int nt = 0; nt < 4; nt++) {
            const float* bp = &Bs[buf][lane & 3][wn * 32 + nt * 8 + (lane >> 2)];
            unsigned bh[2], bl[2];
            split_tf32(bp[0],   bh[0], bl[0]);              // (k, n)
            split_tf32(bp[288], bh[1], bl[1]);              // (k+4, n)   4*72
#pragma unroll
            for (int mt = 0; mt < 2; mt++) {
                mma_tf32(acc[mt][nt], ahf[mt], bh);
                mma_tf32(acc[mt][nt], ahf[mt], bl);
                mma_tf32(acc[mt][nt], alf[mt], bh);
            }
        }
        __syncthreads();
    }

    // ---- epilogue: guarded float2 stores ----
#pragma unroll
    for (int mt = 0; mt < 2; mt++) {
#pragma unroll
        for (int nt = 0; nt < 4; nt++) {
            int r = row0 + wm * 32 + mt * 16 + (lane >> 2);
            int c = col0 + wn * 32 + nt * 8 + (lane & 3) * 2;
            if (c + 1 < N) {
                if (r < M)
                    *(float2*)(out + (long)r * N + c) =
                        make_float2(acc[mt][nt][0], acc[mt][nt][1]);
                if (r + 8 < M)
                    *(float2*)(out + (long)(r + 8) * N + c) =
                        make_float2(acc[mt][nt][2], acc[mt][nt][3]);
            }
        }
    }
}

// ================= alpha + per-head global max =================
template<int H, int C>
__global__ __launch_bounds__(256) void alpha_kernel(
    const float* __restrict__ h, const float* __restrict__ a_s,
    const float* __restrict__ a_d, float* __restrict__ alpha_s,
    float* __restrict__ alpha_d, unsigned* __restrict__ smaxu)
{
    __shared__ unsigned s_max[H];
    if (threadIdx.x < H) s_max[threadIdx.x] = 0u;
    __syncthreads();

    int idx = blockIdx.x * blockDim.x + threadIdx.x;
    if (idx < NNODES * H) {
        int node = idx / H;
        int hh = idx - node * H;
        const float4* hp  = (const float4*)(h + (long)node * H * C + hh * C);
        const float4* asp = (const float4*)(a_s + hh * C);
        const float4* adp = (const float4*)(a_d + hh * C);
        float ss = 0.f, sd = 0.f;
#pragma unroll
        for (int c = 0; c < C / 4; c++) {
            float4 v = hp[c];
            float4 s4 = __ldg(asp + c);
            float4 d4 = __ldg(adp + c);
            ss += v.x * s4.x + v.y * s4.y + v.z * s4.z + v.w * s4.w;
            sd += v.x * d4.x + v.y * d4.y + v.z * d4.z + v.w * d4.w;
        }
        alpha_s[idx] = ss;
        alpha_d[idx] = sd;
        atomicMax(&s_max[hh], enc_f(ss));
    }
    __syncthreads();
    if (threadIdx.x < H)
        atomicMax(&smaxu[threadIdx.x], s_max[threadIdx.x]);
}

// ================= fused edge pass: exp(e - m_ub), CSR-ordered store =================
template<int H>
__global__ __launch_bounds__(256) void edge_fused(
    const int* __restrict__ ei, const int* __restrict__ epos,
    const float* __restrict__ as, const float* __restrict__ ad,
    const unsigned* __restrict__ smaxu, float* __restrict__ ebuf)
{
    int idx = blockIdx.x * blockDim.x + threadIdx.x;
    if (idx >= ETOT * H) return;
    int e  = idx / H;
    int hh = idx - e * H;
    int s, d;
    if (e < NEDGES) { s = __ldg(ei + e); d = __ldg(ei + NEDGES + e); }
    else            { s = e - NEDGES; d = s; }
    float asv = __ldg(as + s * H + hh);
    float adv = __ldg(ad + d * H + hh);
    float ev = asv + adv;
    ev = (ev > 0.f) ? ev : NEG_SLOPE * ev;
    float mb = dec_f(__ldg(smaxu + hh)) + adv;
    mb = (mb > 0.f) ? mb : NEG_SLOPE * mb;
    float ex = __expf(ev - mb);
    int pos = __ldg(epos + e);
    ebuf[(long)pos * H + hh] = ex;      // scattered write (fire-and-forget)
}

// ================= CSR gather + bias + ReLU epilogue =================
template<int H, int C>
__global__ __launch_bounds__(256) void node_gather(
    const int* __restrict__ rowptr, const int* __restrict__ csr_src,
    const float* __restrict__ ex, const float* __restrict__ h,
    const float* __restrict__ bias, float* __restrict__ out,
    unsigned* __restrict__ smaxu)
{
    constexpr int NCH = H * C / 4;
    constexpr int HC  = H * C;
    long idx = (long)blockIdx.x * blockDim.x + threadIdx.x;
    if (idx < MAXH) smaxu[idx] = 0u;
    if (idx >= (long)NNODES * NCH) return;
    int n = (int)(idx / NCH);
    int q = (int)(idx - (long)n * NCH);
    int head = q / (C / 4);

    int beg = __ldg(rowptr + n);
    int end = __ldg(rowptr + n + 1);
    float4 acc = make_float4(0.f, 0.f, 0.f, 0.f);
    float zs = 0.f;
    int j = beg;
    for (; j + 1 < end; j += 2) {
        int s0 = __ldg(csr_src + j);
        int s1 = __ldg(csr_src + j + 1);
        float a0 = __ldg(ex + (long)j * H + head);
        float a1 = __ldg(ex + (long)(j + 1) * H + head);
        float4 h0 = *(const float4*)(h + (long)s0 * HC + q * 4);
        float4 h1 = *(const float4*)(h + (long)s1 * HC + q * 4);
        acc.x += h0.x * a0; acc.y += h0.y * a0;
        acc.z += h0.z * a0; acc.w += h0.w * a0;
        acc.x += h1.x * a1; acc.y += h1.y * a1;
        acc.z += h1.z * a1; acc.w += h1.w * a1;
        zs += a0 + a1;
    }
    if (j < end) {
        int s0 = __ldg(csr_src + j);
        float a0 = __ldg(ex + (long)j * H + head);
        float4 h0 = *(const float4*)(h + (long)s0 * HC + q * 4);
        acc.x += h0.x * a0; acc.y += h0.y * a0;
        acc.z += h0.z * a0; acc.w += h0.w * a0;
        zs += a0;
    }
    float rzv = __frcp_rn(zs);
    const float4 bv = __ldg((const float4*)(bias + q * 4));
    *(float4*)(out + (long)n * HC + q * 4) =
        make_float4(fmaxf(acc.x * rzv + bv.x, 0.f),
                    fmaxf(acc.y * rzv + bv.y, 0.f),
                    fmaxf(acc.z * rzv + bv.z, 0.f),
                    fmaxf(acc.w * rzv + bv.w, 0.f));
}

// ================= per-layer templated driver (minus GEMM) =================
template<int H, int C>
static void run_layer_rest(const float* a_s, const float* a_d, const float* bias,
                           const int* ei, const int* epos,
                           float* h, float* as, float* ad,
                           float* ebuf, unsigned* smaxu,
                           const int* rowptr, const int* csr_src,
                           float* outb)
{
    constexpr int HC = H * C;
    {
        int n = NNODES * H;
        alpha_kernel<H, C><<<(n + 255) / 256, 256>>>(h, a_s, a_d, as, ad, smaxu);
    }
    {
        int n = ETOT * H;
        edge_fused<H><<<(n + 255) / 256, 256>>>(ei, epos, as, ad, smaxu, ebuf);
    }
    {
        long total = (long)NNODES * (HC / 4);
        int blocks = (int)((total + 255) / 256);
        node_gather<H, C><<<blocks, 256>>>(rowptr, csr_src, ebuf, h, bias, outb, smaxu);
    }
}

template<int K, int N>
static void launch_gemm(const float* A, const float* W, float* out) {
    dim3 grid((N + 63) / 64, (NNODES + 127) / 128);
    gemm_tf32_kernel<K, N><<<grid, 256>>>(A, W, out, NNODES);
}

// ================= host orchestration =================
extern "C" void kernel_launch(void* const* d_in, const int* in_sizes, int n_in,
                              void* d_out, int out_size)
{
    const float* x  = (const float*)d_in[0];
    const int*   ei = (const int*)d_in[1];

    float *h, *buf0, *buf1, *as, *ad, *ebuf;
    unsigned* smaxu;
    int *rowptr, *cnt, *fill, *csr_src, *epos, *bsum;
    {
        void* p;
        cudaGetSymbolAddress(&p, g_h);       h       = (float*)p;
        cudaGetSymbolAddress(&p, g_buf0);    buf0    = (float*)p;
        cudaGetSymbolAddress(&p, g_buf1);    buf1    = (float*)p;
        cudaGetSymbolAddress(&p, g_as);      as      = (float*)p;
        cudaGetSymbolAddress(&p, g_ad);      ad      = (float*)p;
        cudaGetSymbolAddress(&p, g_e);       ebuf    = (float*)p;
        cudaGetSymbolAddress(&p, g_smaxu);   smaxu   = (unsigned*)p;
        cudaGetSymbolAddress(&p, g_rowptr);  rowptr  = (int*)p;
        cudaGetSymbolAddress(&p, g_cnt);     cnt     = (int*)p;
        cudaGetSymbolAddress(&p, g_fill);    fill    = (int*)p;
        cudaGetSymbolAddress(&p, g_csr_src); csr_src = (int*)p;
        cudaGetSymbolAddress(&p, g_epos);    epos    = (int*)p;
        cudaGetSymbolAddress(&p, g_bsum);    bsum    = (int*)p;
    }

    const float* W[5]; const float* B[5]; const float* AS[5]; const float* AD[5];
    for (int i = 0; i < 5; i++) {
        W[i]  = (const float*)d_in[3 + 4 * i];
        B[i]  = (const float*)d_in[4 + 4 * i];
        AS[i] = (const float*)d_in[5 + 4 * i];
        AD[i] = (const float*)d_in[6 + 4 * i];
    }

    // ---- CSR build interleaved with layer-0 GEMM (independent) ----
    csr_zero<<<(NNODES + 255) / 256, 256>>>(cnt, fill, smaxu);          // #1
    csr_hist<<<(ETOT + 255) / 256, 256>>>(ei, cnt);                     // #2
    csr_scan1<<<NSCAN, SCAN_BLK>>>(cnt, rowptr, bsum);                  // #3
    launch_gemm< 32, 240>(x, W[0], h);                                  // #4 (profiled)
    csr_scan2<<<1, 128>>>(bsum);                                        // #5
    csr_scan3<<<NSCAN, SCAN_BLK>>>(rowptr, bsum);                       // #6
    csr_fill<<<(ETOT + 255) / 256, 256>>>(ei, rowptr, fill, csr_src, epos); // #7

    // ---- layer 0 rest (gather applies bias B[0] + relu -> buf0) ----
    run_layer_rest<10, 24>(AS[0], AD[0], B[0], ei, epos, h, as, ad, ebuf, smaxu, rowptr, csr_src, buf0);

    // ---- layers 1-4 ----
    launch_gemm<240, 120>(buf0, W[1], h);
    run_layer_rest< 5, 24>(AS[1], AD[1], B[1], ei, epos, h, as, ad, ebuf, smaxu, rowptr, csr_src, buf1);

    launch_gemm<120,  48>(buf1, W[2], h);
    run_layer_rest< 2, 24>(AS[2], AD[2], B[2], ei, epos, h, as, ad, ebuf, smaxu, rowptr, csr_src, buf0);

    launch_gemm< 48,  24>(buf0, W[3], h);
    run_layer_rest< 1, 24>(AS[3], AD[3], B[3], ei, epos, h, as, ad, ebuf, smaxu, rowptr, csr_src, buf1);

    launch_gemm< 24,  12>(buf1, W[4], h);
    run_layer_rest< 1, 12>(AS[4], AD[4], B[4], ei, epos, h, as, ad, ebuf, smaxu, rowptr, csr_src, (float*)d_out);
}

// round 11
// speedup vs baseline: 1.3286x; 1.0215x over previous
#include <cuda_runtime.h>
#include <cuda_bf16.h>

#define NNODES 100000
#define NEDGES 800000
#define ETOT   900000
#define MAXHC  240
#define MAXH   10
#define NEG_SLOPE 0.2f
#define SCAN_BLK 1024
#define NSCAN ((NNODES + SCAN_BLK - 1) / SCAN_BLK)   // 98

// ---------------- scratch (device globals; no allocation allowed) ----------------
__device__ float    g_h   [NNODES * MAXHC];
__device__ float    g_buf0[NNODES * MAXHC];
__device__ float    g_buf1[NNODES * MAXHC];
__device__ float    g_as  [NNODES * MAXH];
__device__ float    g_ad  [NNODES * MAXH];
__device__ float    g_e   [ETOT   * MAXH];      // per-edge exp values (CSR order)
__device__ unsigned g_smaxu[MAXH];              // per-head global max (encoded)
// CSR (built once per launch)
__device__ int g_rowptr [NNODES + 1];
__device__ int g_cnt    [NNODES];
__device__ int g_fill   [NNODES];
__device__ int g_csr_src[ETOT];
__device__ int g_epos   [ETOT];                 // edge id -> csr position
__device__ int g_bsum   [NSCAN];

// ---------------- helpers ----------------
__device__ __forceinline__ unsigned enc_f(float v) {
    unsigned u = __float_as_uint(v);
    return (u & 0x80000000u) ? ~u : (u | 0x80000000u);
}
__device__ __forceinline__ float dec_f(unsigned u) {
    return __uint_as_float((u & 0x80000000u) ? (u ^ 0x80000000u) : ~u);
}

// split fp32 into two tf32 values (3xTF32 trick); x - hi is exact in fp32.
__device__ __forceinline__ void split_tf32(float x, unsigned& hi, unsigned& lo) {
    asm("cvt.rna.tf32.f32 %0, %1;" : "=r"(hi) : "f"(x));
    float r = x - __uint_as_float(hi);
    asm("cvt.rna.tf32.f32 %0, %1;" : "=r"(lo) : "f"(r));
}

__device__ __forceinline__ void mma_tf32(float* d, const unsigned* a, const unsigned* b) {
    asm volatile("mma.sync.aligned.m16n8k8.row.col.f32.tf32.tf32.f32 "
        "{%0,%1,%2,%3}, {%4,%5,%6,%7}, {%8,%9}, {%0,%1,%2,%3};"
        : "+f"(d[0]), "+f"(d[1]), "+f"(d[2]), "+f"(d[3])
        : "r"(a[0]), "r"(a[1]), "r"(a[2]), "r"(a[3]), "r"(b[0]), "r"(b[1]));
}

#define CP_ASYNC16(dst, src, sz) \
    asm volatile("cp.async.ca.shared.global [%0], [%1], 16, %2;" \
                 :: "r"(dst), "l"(src), "r"(sz) : "memory")
#define CP_COMMIT()  asm volatile("cp.async.commit_group;" ::: "memory")
#define CP_WAIT0()   asm volatile("cp.async.wait_group 0;" ::: "memory")

// ================= CSR build (once per launch) =================
__global__ __launch_bounds__(256) void csr_zero(int* cnt, int* fill, unsigned* smaxu) {
    int i = blockIdx.x * blockDim.x + threadIdx.x;
    if (i < NNODES) { cnt[i] = 0; fill[i] = 0; }
    if (i < MAXH) smaxu[i] = 0u;
}

__global__ __launch_bounds__(256) void csr_hist(const int* __restrict__ ei, int* cnt) {
    int e = blockIdx.x * blockDim.x + threadIdx.x;
    if (e >= ETOT) return;
    int d = (e < NEDGES) ? __ldg(ei + NEDGES + e) : (e - NEDGES);
    atomicAdd(&cnt[d], 1);
}

__global__ __launch_bounds__(SCAN_BLK) void csr_scan1(const int* __restrict__ cnt,
                                                      int* rowptr, int* bsum) {
    __shared__ int sh[SCAN_BLK];
    int gi = blockIdx.x * SCAN_BLK + threadIdx.x;
    int v = (gi < NNODES) ? cnt[gi] : 0;
    sh[threadIdx.x] = v;
    __syncthreads();
    for (int off = 1; off < SCAN_BLK; off <<= 1) {
        int t = (threadIdx.x >= off) ? sh[threadIdx.x - off] : 0;
        __syncthreads();
        sh[threadIdx.x] += t;
        __syncthreads();
    }
    if (gi < NNODES) rowptr[gi] = sh[threadIdx.x] - v;
    if (threadIdx.x == SCAN_BLK - 1) bsum[blockIdx.x] = sh[threadIdx.x];
}

__global__ __launch_bounds__(128) void csr_scan2(int* bsum) {
    __shared__ int sh[128];
    int v = (threadIdx.x < NSCAN) ? bsum[threadIdx.x] : 0;
    sh[threadIdx.x] = v;
    __syncthreads();
    for (int off = 1; off < 128; off <<= 1) {
        int t = (threadIdx.x >= off) ? sh[threadIdx.x - off] : 0;
        __syncthreads();
        sh[threadIdx.x] += t;
        __syncthreads();
    }
    if (threadIdx.x < NSCAN) bsum[threadIdx.x] = sh[threadIdx.x] - v;
}

__global__ __launch_bounds__(SCAN_BLK) void csr_scan3(int* rowptr, const int* __restrict__ bsum) {
    int gi = blockIdx.x * SCAN_BLK + threadIdx.x;
    if (gi < NNODES) rowptr[gi] += bsum[blockIdx.x];
    if (gi == 0) rowptr[NNODES] = ETOT;
}

__global__ __launch_bounds__(256) void csr_fill(const int* __restrict__ ei,
                                                const int* __restrict__ rowptr,
                                                int* fill, int* csr_src, int* epos) {
    int e = blockIdx.x * blockDim.x + threadIdx.x;
    if (e >= ETOT) return;
    int s, d;
    if (e < NEDGES) { s = __ldg(ei + e); d = __ldg(ei + NEDGES + e); }
    else            { s = e - NEDGES; d = s; }
    int pos = rowptr[d] + atomicAdd(&fill[d], 1);
    csr_src[pos] = s;
    epos[e] = pos;
}

// ================= tf32 tensor-core GEMM: out[M,N] = A[M,K] @ W[K,N] =================
// Block 128x64, 8 warps (4m x 2n), warp tile 32x32 (2x4 m16n8 frags).
// A: cp.async double-buffered raw, per-fragment 3xTF32 split.
// B: register-prefetched, pre-split ONCE per tile into smem hi/lo planes.
template<int K, int N>
__global__ __launch_bounds__(256, 3) void gemm_tf32_kernel(
    const float* __restrict__ A, const float* __restrict__ W,
    float* __restrict__ out, int M)
{
    __shared__ float    As[2][128][12];   // raw A [row][k0..7], pad 12
    __shared__ unsigned Bh[2][8][72];     // tf32 hi of B [k][n], pad 72
    __shared__ unsigned Bl[2][8][72];     // tf32 lo of B

    const int tid  = threadIdx.x;
    const int lane = tid & 31;
    const int warp = tid >> 5;
    const int wm   = warp & 3;
    const int wn   = warp >> 2;
    const int row0 = blockIdx.y * 128;
    const int col0 = blockIdx.x * 64;

    float acc[2][4][4];
#pragma unroll
    for (int mt = 0; mt < 2; mt++)
#pragma unroll
        for (int nt = 0; nt < 4; nt++)
#pragma unroll
            for (int i = 0; i < 4; i++) acc[mt][nt][i] = 0.f;

    // ---- A cp.async setup ----
    const int arow = tid >> 1;
    const int ah4  = (tid & 1) * 4;
    const int gr   = row0 + arow;
    const unsigned a_sz = (gr < M) ? 16u : 0u;
    const float* a_src = A + (long)(gr < M ? gr : 0) * K + ah4;
    unsigned a_dst[2];
    a_dst[0] = (unsigned)__cvta_generic_to_shared(&As[0][arow][ah4]);
    a_dst[1] = (unsigned)__cvta_generic_to_shared(&As[1][arow][ah4]);

    // ---- B register-prefetch setup (tid<128 active) ----
    const int bk   = (tid & 127) >> 4;      // 0..7
    const int bnc  = tid & 15;              // 0..15 -> 4 floats each
    const int gcol = col0 + bnc * 4;
    const int rem  = N - gcol;

    auto ldg_b = [&](int k0) -> float4 {
        float4 v = make_float4(0.f, 0.f, 0.f, 0.f);
        if (tid < 128 && rem > 0) {
            const float* p = W + (long)(k0 + bk) * N + gcol;
            if (rem >= 4) v = *(const float4*)p;
            else { v.x = p[0]; if (rem > 1) v.y = p[1]; if (rem > 2) v.z = p[2]; }
        }
        return v;
    };
    auto store_b = [&](int buf, float4 v) {
        if (tid < 128) {
            unsigned h0, l0, h1, l1, h2, l2, h3, l3;
            split_tf32(v.x, h0, l0); split_tf32(v.y, h1, l1);
            split_tf32(v.z, h2, l2); split_tf32(v.w, h3, l3);
            unsigned* ph = &Bh[buf][bk][bnc * 4];
            unsigned* pl = &Bl[buf][bk][bnc * 4];
            ph[0] = h0; ph[1] = h1; ph[2] = h2; ph[3] = h3;
            pl[0] = l0; pl[1] = l1; pl[2] = l2; pl[3] = l3;
        }
    };

    constexpr int NK = K / 8;

    // ---- prologue: stage 0 ----
    CP_ASYNC16(a_dst[0], a_src, a_sz);
    CP_COMMIT();
    store_b(0, ldg_b(0));
    CP_WAIT0();
    __syncthreads();

#pragma unroll 1
    for (int s = 0; s < NK; s++) {
        const bool more = (s + 1 < NK);
        float4 bn;
        if (more) {
            const int k0n = (s + 1) * 8;
            CP_ASYNC16(a_dst[(s + 1) & 1], a_src + k0n, a_sz);
            CP_COMMIT();
            bn = ldg_b(k0n);
        }

        const int buf = s & 1;
        // A fragments (hi/lo) for 2 m-tiles
        unsigned ahf[2][4], alf[2][4];
#pragma unroll
        for (int mt = 0; mt < 2; mt++) {
            const float* ap = &As[buf][wm * 32 + mt * 16 + (lane >> 2)][lane & 3];
            split_tf32(ap[0],   ahf[mt][0], alf[mt][0]);
            split_tf32(ap[96],  ahf[mt][1], alf[mt][1]);
            split_tf32(ap[4],   ahf[mt][2], alf[mt][2]);
            split_tf32(ap[100], ahf[mt][3], alf[mt][3]);
        }
        // B fragments: plain lds.u32 from pre-split planes
#pragma unroll
        for (int nt = 0; nt < 4; nt++) {
            const int ci = wn * 32 + nt * 8 + (lane >> 2);
            const int ki = lane & 3;
            unsigned bh[2], bl[2];
            bh[0] = Bh[buf][ki][ci];     bh[1] = Bh[buf][ki + 4][ci];
            bl[0] = Bl[buf][ki][ci];     bl[1] = Bl[buf][ki + 4][ci];
#pragma unroll
            for (int mt = 0; mt < 2; mt++) {
                mma_tf32(acc[mt][nt], ahf[mt], bh);
                mma_tf32(acc[mt][nt], ahf[mt], bl);
                mma_tf32(acc[mt][nt], alf[mt], bh);
            }
        }

        if (more) {
            store_b((s + 1) & 1, bn);   // writes alternate buffer — safe pre-sync
            CP_WAIT0();
            __syncthreads();
        }
    }

    // ---- epilogue: guarded float2 stores ----
#pragma unroll
    for (int mt = 0; mt < 2; mt++) {
#pragma unroll
        for (int nt = 0; nt < 4; nt++) {
            int r = row0 + wm * 32 + mt * 16 + (lane >> 2);
            int c = col0 + wn * 32 + nt * 8 + (lane & 3) * 2;
            if (c + 1 < N) {
                if (r < M)
                    *(float2*)(out + (long)r * N + c) =
                        make_float2(acc[mt][nt][0], acc[mt][nt][1]);
                if (r + 8 < M)
                    *(float2*)(out + (long)(r + 8) * N + c) =
                        make_float2(acc[mt][nt][2], acc[mt][nt][3]);
            }
        }
    }
}

// ================= alpha + per-head global max =================
template<int H, int C>
__global__ __launch_bounds__(256) void alpha_kernel(
    const float* __restrict__ h, const float* __restrict__ a_s,
    const float* __restrict__ a_d, float* __restrict__ alpha_s,
    float* __restrict__ alpha_d, unsigned* __restrict__ smaxu)
{
    __shared__ unsigned s_max[H];
    if (threadIdx.x < H) s_max[threadIdx.x] = 0u;
    __syncthreads();

    int idx = blockIdx.x * blockDim.x + threadIdx.x;
    if (idx < NNODES * H) {
        int node = idx / H;
        int hh = idx - node * H;
        const float4* hp  = (const float4*)(h + (long)node * H * C + hh * C);
        const float4* asp = (const float4*)(a_s + hh * C);
        const float4* adp = (const float4*)(a_d + hh * C);
        float ss = 0.f, sd = 0.f;
#pragma unroll
        for (int c = 0; c < C / 4; c++) {
            float4 v = hp[c];
            float4 s4 = __ldg(asp + c);
            float4 d4 = __ldg(adp + c);
            ss += v.x * s4.x + v.y * s4.y + v.z * s4.z + v.w * s4.w;
            sd += v.x * d4.x + v.y * d4.y + v.z * d4.z + v.w * d4.w;
        }
        alpha_s[idx] = ss;
        alpha_d[idx] = sd;
        atomicMax(&s_max[hh], enc_f(ss));
    }
    __syncthreads();
    if (threadIdx.x < H)
        atomicMax(&smaxu[threadIdx.x], s_max[threadIdx.x]);
}

// ================= fused edge pass: exp(e - m_ub), CSR-ordered store =================
template<int H>
__global__ __launch_bounds__(256) void edge_fused(
    const int* __restrict__ ei, const int* __restrict__ epos,
    const float* __restrict__ as, const float* __restrict__ ad,
    const unsigned* __restrict__ smaxu, float* __restrict__ ebuf)
{
    int idx = blockIdx.x * blockDim.x + threadIdx.x;
    if (idx >= ETOT * H) return;
    int e  = idx / H;
    int hh = idx - e * H;
    int s, d;
    if (e < NEDGES) { s = __ldg(ei + e); d = __ldg(ei + NEDGES + e); }
    else            { s = e - NEDGES; d = s; }
    float asv = __ldg(as + s * H + hh);
    float adv = __ldg(ad + d * H + hh);
    float ev = asv + adv;
    ev = (ev > 0.f) ? ev : NEG_SLOPE * ev;
    float mb = dec_f(__ldg(smaxu + hh)) + adv;
    mb = (mb > 0.f) ? mb : NEG_SLOPE * mb;
    float ex = __expf(ev - mb);
    int pos = __ldg(epos + e);
    ebuf[(long)pos * H + hh] = ex;      // scattered write (fire-and-forget)
}

// ================= CSR gather + bias + ReLU epilogue =================
template<int H, int C>
__global__ __launch_bounds__(256) void node_gather(
    const int* __restrict__ rowptr, const int* __restrict__ csr_src,
    const float* __restrict__ ex, const float* __restrict__ h,
    const float* __restrict__ bias, float* __restrict__ out,
    unsigned* __restrict__ smaxu)
{
    constexpr int NCH = H * C / 4;
    constexpr int HC  = H * C;
    long idx = (long)blockIdx.x * blockDim.x + threadIdx.x;
    if (idx < MAXH) smaxu[idx] = 0u;
    if (idx >= (long)NNODES * NCH) return;
    int n = (int)(idx / NCH);
    int q = (int)(idx - (long)n * NCH);
    int head = q / (C / 4);

    int beg = __ldg(rowptr + n);
    int end = __ldg(rowptr + n + 1);
    float4 acc = make_float4(0.f, 0.f, 0.f, 0.f);
    float zs = 0.f;
    int j = beg;
    for (; j + 1 < end; j += 2) {
        int s0 = __ldg(csr_src + j);
        int s1 = __ldg(csr_src + j + 1);
        float a0 = __ldg(ex + (long)j * H + head);
        float a1 = __ldg(ex + (long)(j + 1) * H + head);
        float4 h0 = *(const float4*)(h + (long)s0 * HC + q * 4);
        float4 h1 = *(const float4*)(h + (long)s1 * HC + q * 4);
        acc.x += h0.x * a0; acc.y += h0.y * a0;
        acc.z += h0.z * a0; acc.w += h0.w * a0;
        acc.x += h1.x * a1; acc.y += h1.y * a1;
        acc.z += h1.z * a1; acc.w += h1.w * a1;
        zs += a0 + a1;
    }
    if (j < end) {
        int s0 = __ldg(csr_src + j);
        float a0 = __ldg(ex + (long)j * H + head);
        float4 h0 = *(const float4*)(h + (long)s0 * HC + q * 4);
        acc.x += h0.x * a0; acc.y += h0.y * a0;
        acc.z += h0.z * a0; acc.w += h0.w * a0;
        zs += a0;
    }
    float rzv = __frcp_rn(zs);
    const float4 bv = __ldg((const float4*)(bias + q * 4));
    *(float4*)(out + (long)n * HC + q * 4) =
        make_float4(fmaxf(acc.x * rzv + bv.x, 0.f),
                    fmaxf(acc.y * rzv + bv.y, 0.f),
                    fmaxf(acc.z * rzv + bv.z, 0.f),
                    fmaxf(acc.w * rzv + bv.w, 0.f));
}

// ================= per-layer templated driver (minus GEMM) =================
template<int H, int C>
static void run_layer_rest(const float* a_s, const float* a_d, const float* bias,
                           const int* ei, const int* epos,
                           float* h, float* as, float* ad,
                           float* ebuf, unsigned* smaxu,
                           const int* rowptr, const int* csr_src,
                           float* outb)
{
    constexpr int HC = H * C;
    {
        int n = NNODES * H;
        alpha_kernel<H, C><<<(n + 255) / 256, 256>>>(h, a_s, a_d, as, ad, smaxu);
    }
    {
        int n = ETOT * H;
        edge_fused<H><<<(n + 255) / 256, 256>>>(ei, epos, as, ad, smaxu, ebuf);
    }
    {
        long total = (long)NNODES * (HC / 4);
        int blocks = (int)((total + 255) / 256);
        node_gather<H, C><<<blocks, 256>>>(rowptr, csr_src, ebuf, h, bias, outb, smaxu);
    }
}

template<int K, int N>
static void launch_gemm(const float* A, const float* W, float* out) {
    dim3 grid((N + 63) / 64, (NNODES + 127) / 128);
    gemm_tf32_kernel<K, N><<<grid, 256>>>(A, W, out, NNODES);
}

// ================= host orchestration =================
extern "C" void kernel_launch(void* const* d_in, const int* in_sizes, int n_in,
                              void* d_out, int out_size)
{
    const float* x  = (const float*)d_in[0];
    const int*   ei = (const int*)d_in[1];

    float *h, *buf0, *buf1, *as, *ad, *ebuf;
    unsigned* smaxu;
    int *rowptr, *cnt, *fill, *csr_src, *epos, *bsum;
    {
        void* p;
        cudaGetSymbolAddress(&p, g_h);       h       = (float*)p;
        cudaGetSymbolAddress(&p, g_buf0);    buf0    = (float*)p;
        cudaGetSymbolAddress(&p, g_buf1);    buf1    = (float*)p;
        cudaGetSymbolAddress(&p, g_as);      as      = (float*)p;
        cudaGetSymbolAddress(&p, g_ad);      ad      = (float*)p;
        cudaGetSymbolAddress(&p, g_e);       ebuf    = (float*)p;
        cudaGetSymbolAddress(&p, g_smaxu);   smaxu   = (unsigned*)p;
        cudaGetSymbolAddress(&p, g_rowptr);  rowptr  = (int*)p;
        cudaGetSymbolAddress(&p, g_cnt);     cnt     = (int*)p;
        cudaGetSymbolAddress(&p, g_fill);    fill    = (int*)p;
        cudaGetSymbolAddress(&p, g_csr_src); csr_src = (int*)p;
        cudaGetSymbolAddress(&p, g_epos);    epos    = (int*)p;
        cudaGetSymbolAddress(&p, g_bsum);    bsum    = (int*)p;
    }

    const float* W[5]; const float* B[5]; const float* AS[5]; const float* AD[5];
    for (int i = 0; i < 5; i++) {
        W[i]  = (const float*)d_in[3 + 4 * i];
        B[i]  = (const float*)d_in[4 + 4 * i];
        AS[i] = (const float*)d_in[5 + 4 * i];
        AD[i] = (const float*)d_in[6 + 4 * i];
    }

    // ---- CSR build interleaved with layer-0 GEMM (independent) ----
    csr_zero<<<(NNODES + 255) / 256, 256>>>(cnt, fill, smaxu);          // #1
    csr_hist<<<(ETOT + 255) / 256, 256>>>(ei, cnt);                     // #2
    csr_scan1<<<NSCAN, SCAN_BLK>>>(cnt, rowptr, bsum);                  // #3
    launch_gemm< 32, 240>(x, W[0], h);                                  // #4 (profiled)
    csr_scan2<<<1, 128>>>(bsum);                                        // #5
    csr_scan3<<<NSCAN, SCAN_BLK>>>(rowptr, bsum);                       // #6
    csr_fill<<<(ETOT + 255) / 256, 256>>>(ei, rowptr, fill, csr_src, epos); // #7

    // ---- layer 0 rest (gather applies bias B[0] + relu -> buf0) ----
    run_layer_rest<10, 24>(AS[0], AD[0], B[0], ei, epos, h, as, ad, ebuf, smaxu, rowptr, csr_src, buf0);

    // ---- layers 1-4 ----
    launch_gemm<240, 120>(buf0, W[1], h);
    run_layer_rest< 5, 24>(AS[1], AD[1], B[1], ei, epos, h, as, ad, ebuf, smaxu, rowptr, csr_src, buf1);

    launch_gemm<120,  48>(buf1, W[2], h);
    run_layer_rest< 2, 24>(AS[2], AD[2], B[2], ei, epos, h, as, ad, ebuf, smaxu, rowptr, csr_src, buf0);

    launch_gemm< 48,  24>(buf0, W[3], h);
    run_layer_rest< 1, 24>(AS[3], AD[3], B[3], ei, epos, h, as, ad, ebuf, smaxu, rowptr, csr_src, buf1);

    launch_gemm< 24,  12>(buf1, W[4], h);
    run_layer_rest< 1, 12>(AS[4], AD[4], B[4], ei, epos, h, as, ad, ebuf, smaxu, rowptr, csr_src, (float*)d_out);
}